// round 14
// baseline (speedup 1.0000x reference)
#include <cuda_runtime.h>
#include <cuda_fp16.h>
#include <math.h>
#include <stdint.h>

// ---------------------------------------------------------------------------
// Problem constants
// ---------------------------------------------------------------------------
#define T_STEPS 256
#define BATCH   16
#define HID     4096          // H
#define PROJ    512           // P
#define G4H     16384         // 4*H
#define F1      532
#define F2CON   768           // con_x features (1280-512)
#define NBLK    128           // persistent grid size
#define HSTR    20            // padded smem row stride (floats) for proj h tiles

#define TSTR 136              // tf32 sgemm smem stride (floats)

// persistent-kernel dynamic smem (floats):
//  pb1s (persistent, 16384 uint2) [0, 32768)
//  phase region base PH = 32768:
//   gate: af (uint32) [PH, PH+8192) | zbuf1 [PH+8192,+2048) | zbuf2 [PH+10240,+2048)
//   proj: gpf1 [PH,+2560) | gpf2 [PH+2560,+2560) | predu1 [PH+5120,+9216) | predu2 [PH+14336,+9216)
#define SM_PH       32768
#define SM_TOTAL_F  56320
#define SM_TOTAL_B  (SM_TOTAL_F * 4)     // 225280

// ---------------------------------------------------------------------------
// Device scratch (static only — no cudaMalloc allowed)
// ---------------------------------------------------------------------------
__device__ float g_xg1[(size_t)T_STEPS * BATCH * G4H];   // 268 MB
__device__ float g_xg2[(size_t)T_STEPS * BATCH * G4H];   // 268 MB
// gate weights packed in m16n8k16 B-fragment order (fp16):
// pb1[nt][c][lane] = uint2{ half2(W[n][k0],W[n][k0+1]), half2(W[n][k0+8],W[n][k0+9]) }
//   n = nt*8 + lane/4, k0 = 16c + 2*(lane%4)
// pb2 packed PAIRWISE for uint4 loads:
//   pb2[((nt*32 + cp)*64) + lane*2 + h] = fragment of chunk (2cp+h)
__device__ uint2 g_pb1[(size_t)2048 * 32 * 32];          // 16 MB (L1: K=512)
__device__ uint2 g_pb2[(size_t)2048 * 64 * 32];          // 32 MB (L2: K=1024)
__device__ float g_Wtr1[(size_t)HID * PROJ];             // W_hr1^T [k][p] fp32 (8 MB)
__device__ float g_Wtr2[(size_t)HID * PROJ];
__device__ float g_out1[(size_t)(T_STEPS + 1) * BATCH * PROJ];
__device__ float g_out2[(size_t)(T_STEPS + 1) * BATCH * PROJ];
__device__ float g_c1[BATCH * HID];
__device__ float g_c2[BATCH * HID];
__device__ float g_g1h[BATCH * HID];
__device__ float g_g2h[BATCH * HID];
__device__ int   g_counts[T_STEPS];
__device__ int   g_offsets[T_STEPS + 1];

__device__ volatile unsigned g_genv;   // monotonic across replays
__device__ unsigned g_arrive;          // self-resetting

// ---------------------------------------------------------------------------
// packed f32x2 helpers (proj path)
// ---------------------------------------------------------------------------
__device__ __forceinline__ unsigned long long pk2(float x, float y) {
    unsigned long long d;
    asm("mov.b64 %0, {%1, %2};" : "=l"(d) : "f"(x), "f"(y));
    return d;
}
__device__ __forceinline__ void fma2(unsigned long long& a, unsigned long long b,
                                     unsigned long long c) {
    asm("fma.rn.f32x2 %0, %1, %2, %0;" : "+l"(a) : "l"(b), "l"(c));
}
__device__ __forceinline__ unsigned long long add2(unsigned long long a,
                                                   unsigned long long b) {
    unsigned long long d;
    asm("add.rn.f32x2 %0, %1, %2;" : "=l"(d) : "l"(a), "l"(b));
    return d;
}
__device__ __forceinline__ float2 up2(unsigned long long d) {
    float2 r;
    asm("mov.b64 {%0, %1}, %2;" : "=f"(r.x), "=f"(r.y) : "l"(d));
    return r;
}
__device__ __forceinline__ float sigf(float x) { return 1.f / (1.f + expf(-x)); }

__device__ __forceinline__ uint32_t h2u(float2 f) {
    __half2 h = __float22half2_rn(f);
    return *(uint32_t*)&h;
}

// ---------------------------------------------------------------------------
// fp16 HMMA m16n8k16 (fp32 accumulate)
// ---------------------------------------------------------------------------
__device__ __forceinline__ void mma_f16(float c[4], const uint32_t a[4],
                                        const uint32_t b[2]) {
    asm volatile(
        "mma.sync.aligned.m16n8k16.row.col.f32.f16.f16.f32 "
        "{%0,%1,%2,%3}, {%4,%5,%6,%7}, {%8,%9}, {%0,%1,%2,%3};\n"
        : "+f"(c[0]), "+f"(c[1]), "+f"(c[2]), "+f"(c[3])
        : "r"(a[0]), "r"(a[1]), "r"(a[2]), "r"(a[3]), "r"(b[0]), "r"(b[1]));
}

// ---------------------------------------------------------------------------
// tf32 helpers (3xTF32 split GEMM, Phase A)
// ---------------------------------------------------------------------------
__device__ __forceinline__ uint32_t f2tf(float x) {
    uint32_t r;
    asm("cvt.rna.tf32.f32 %0, %1;" : "=r"(r) : "f"(x));
    return r;
}
__device__ __forceinline__ void mma_tf32(float c[4], const uint32_t a[4],
                                         const uint32_t b[2]) {
    asm volatile(
        "mma.sync.aligned.m16n8k8.row.col.f32.tf32.tf32.f32 "
        "{%0,%1,%2,%3}, {%4,%5,%6,%7}, {%8,%9}, {%0,%1,%2,%3};\n"
        : "+f"(c[0]), "+f"(c[1]), "+f"(c[2]), "+f"(c[3])
        : "r"(a[0]), "r"(a[1]), "r"(a[2]), "r"(a[3]), "r"(b[0]), "r"(b[1]));
}

// ---------------------------------------------------------------------------
// grid-wide barrier
// ---------------------------------------------------------------------------
__device__ __forceinline__ void gsync(unsigned& gen) {
    __syncthreads();
    if (threadIdx.x == 0) {
        unsigned next = gen + 1;
        __threadfence();
        if (atomicAdd(&g_arrive, 1u) == (unsigned)(NBLK - 1)) {
            g_arrive = 0u;
            __threadfence();
            g_genv = next;
        } else {
            while (g_genv != next) {}
            __threadfence();
        }
        gen = next;
    }
    __syncthreads();
}

// ---------------------------------------------------------------------------
// Fused prep: pack gate weights into HMMA fragment order (fp16),
// transpose proj weights (fp32), zero states, packed-seq counts.
// blocks: [0,2048) pb1 | [2048,4096) pb2 | [4096,6144) Wtr1 | [6144,8192) Wtr2
//         8192 counts | (8192,10241) zero
// ---------------------------------------------------------------------------
__global__ void prep_kernel(const float* __restrict__ W_hh1,
                            const float* __restrict__ W_ih2,
                            const float* __restrict__ W_hh2,
                            const float* __restrict__ W_hr1,
                            const float* __restrict__ W_hr2,
                            const int* __restrict__ lens) {
    int bid = blockIdx.x;
    int tid = threadIdx.x;
    if (bid < 2048) {                       // pb1: nt = bid, 32 chunks
        int nt = bid;
        #pragma unroll
        for (int j = 0; j < 4; j++) {
            int i = tid + j * 256;          // 0..1023
            int c = i >> 5, lane = i & 31;
            int gr = lane >> 2, tc = lane & 3;
            int n = nt * 8 + gr;
            int k0 = 16 * c + 2 * tc;
            const float* src = W_hh1 + (size_t)n * 512;
            float2 f0 = *(const float2*)(src + k0);
            float2 f1 = *(const float2*)(src + k0 + 8);
            g_pb1[(size_t)(nt * 32 + c) * 32 + lane] = make_uint2(h2u(f0), h2u(f1));
        }
    } else if (bid < 4096) {                // pb2: nt = bid-2048, 64 chunks, pairwise
        int nt = bid - 2048;
        #pragma unroll
        for (int j = 0; j < 8; j++) {
            int i = tid + j * 256;          // 0..2047
            int c = i >> 5, lane = i & 31;
            int gr = lane >> 2, tc = lane & 3;
            int n = nt * 8 + gr;
            int k0 = 16 * c + 2 * tc;
            const float* src = (c < 32) ? (W_ih2 + (size_t)n * 1280 + k0)
                                        : (W_hh2 + (size_t)n * 512 + (k0 - 512));
            float2 f0 = *(const float2*)src;
            float2 f1 = *(const float2*)(src + 8);
            // pairwise layout: [((nt*32 + c/2)*64) + lane*2 + (c&1)]
            g_pb2[(size_t)(nt * 32 + (c >> 1)) * 64 + lane * 2 + (c & 1)] =
                make_uint2(h2u(f0), h2u(f1));
        }
    } else if (bid < 8192) {                // proj transposes (32x33 tiles)
        __shared__ float tile[32][33];
        const float* in;
        float* out;
        int tix;
        if (bid < 6144) { in = W_hr1; out = g_Wtr1; tix = bid - 4096; }
        else            { in = W_hr2; out = g_Wtr2; tix = bid - 6144; }
        const int rows = 512, ldin = HID;
        int nbx = rows >> 5;                // 16
        int bx = tix % nbx, by = tix / nbx;
        int j0 = bx * 32, k0 = by * 32;
        int tx = tid & 31, ty = tid >> 5;
        #pragma unroll
        for (int i = 0; i < 32; i += 8) {
            int j = j0 + ty + i, k = k0 + tx;
            tile[ty + i][tx] = in[(size_t)j * ldin + k];
        }
        __syncthreads();
        #pragma unroll
        for (int i = 0; i < 32; i += 8) {
            int k = k0 + ty + i, j = j0 + tx;
            out[(size_t)k * rows + j] = tile[tx][ty + i];
        }
    } else if (bid == 8192) {               // counts
        int t = tid;
        int c = 0;
        #pragma unroll
        for (int b = 0; b < BATCH; b++) c += (lens[b] > t) ? 1 : 0;
        g_counts[t] = c;
        __syncthreads();
        if (t == 0) {
            int s = 0;
            for (int i = 0; i < T_STEPS; i++) { g_offsets[i] = s; s += g_counts[i]; }
            g_offsets[T_STEPS] = s;
        }
    } else {                                // zero
        const size_t n1 = (size_t)(T_STEPS + 1) * BATCH * PROJ;
        const size_t nc = (size_t)BATCH * HID;
        const size_t tot = 2 * n1 + 2 * nc;
        size_t base = (size_t)(bid - 8193) * 256 + tid;
        for (size_t i = base; i < tot; i += (size_t)2048 * 256) {
            if (i < n1)               g_out1[i] = 0.f;
            else if (i < 2 * n1)      g_out2[i - n1] = 0.f;
            else if (i < 2 * n1 + nc) g_c1[i - 2 * n1] = 0.f;
            else                      g_c2[i - 2 * n1 - nc] = 0.f;
        }
    }
}

// ---------------------------------------------------------------------------
// Phase A GEMM on tensor cores: 3xTF32 (fp32-grade accuracy).
// ---------------------------------------------------------------------------
__global__ void __launch_bounds__(256)
sgemm_tf32(const float* __restrict__ A, const float* __restrict__ B,
           const float* __restrict__ bias, float* __restrict__ C,
           int K, int lda, int ldb, int boff) {
    __shared__ float Ah[16 * TSTR], Al[16 * TSTR];
    __shared__ float Bh[16 * TSTR], Bl[16 * TSTR];

    const int tid = threadIdx.x;
    const int m0 = blockIdx.y * 128, n0 = blockIdx.x * 128;
    const int warp = tid >> 5, lane = tid & 31;
    const int wm = (warp >> 2) * 64;
    const int wn = (warp & 3) * 32;
    const int g  = lane >> 2;
    const int tk = lane & 3;

    float c[4][4][4];
    #pragma unroll
    for (int mt = 0; mt < 4; mt++)
        #pragma unroll
        for (int nt = 0; nt < 4; nt++)
            #pragma unroll
            for (int i = 0; i < 4; i++) c[mt][nt][i] = 0.f;

    const int rr = tid >> 4;
    const int cc = tid & 15;

    for (int k0 = 0; k0 < K; k0 += 16) {
        __syncthreads();
        const bool kv = (k0 + cc) < K;
        #pragma unroll
        for (int i = 0; i < 8; i++) {
            int r = rr + i * 16;
            float av = kv ? A[(size_t)(m0 + r) * lda + k0 + cc] : 0.f;
            float bv = kv ? B[(size_t)(n0 + r) * ldb + boff + k0 + cc] : 0.f;
            uint32_t ah = f2tf(av);
            uint32_t bh = f2tf(bv);
            Ah[cc * TSTR + r] = __uint_as_float(ah);
            Al[cc * TSTR + r] = __uint_as_float(f2tf(av - __uint_as_float(ah)));
            Bh[cc * TSTR + r] = __uint_as_float(bh);
            Bl[cc * TSTR + r] = __uint_as_float(f2tf(bv - __uint_as_float(bh)));
        }
        __syncthreads();

        #pragma unroll
        for (int ks = 0; ks < 16; ks += 8) {
            const int kk = ks + tk;
            uint32_t ahf[4][4], alf[4][4], bhf[4][2], blf[4][2];
            #pragma unroll
            for (int mt = 0; mt < 4; mt++) {
                int rb = wm + mt * 16 + g;
                ahf[mt][0] = __float_as_uint(Ah[kk * TSTR + rb]);
                ahf[mt][1] = __float_as_uint(Ah[kk * TSTR + rb + 8]);
                ahf[mt][2] = __float_as_uint(Ah[(kk + 4) * TSTR + rb]);
                ahf[mt][3] = __float_as_uint(Ah[(kk + 4) * TSTR + rb + 8]);
                alf[mt][0] = __float_as_uint(Al[kk * TSTR + rb]);
                alf[mt][1] = __float_as_uint(Al[kk * TSTR + rb + 8]);
                alf[mt][2] = __float_as_uint(Al[(kk + 4) * TSTR + rb]);
                alf[mt][3] = __float_as_uint(Al[(kk + 4) * TSTR + rb + 8]);
            }
            #pragma unroll
            for (int nt = 0; nt < 4; nt++) {
                int nb = wn + nt * 8 + g;
                bhf[nt][0] = __float_as_uint(Bh[kk * TSTR + nb]);
                bhf[nt][1] = __float_as_uint(Bh[(kk + 4) * TSTR + nb]);
                blf[nt][0] = __float_as_uint(Bl[kk * TSTR + nb]);
                blf[nt][1] = __float_as_uint(Bl[(kk + 4) * TSTR + nb]);
            }
            #pragma unroll
            for (int mt = 0; mt < 4; mt++)
                #pragma unroll
                for (int nt = 0; nt < 4; nt++) {
                    mma_tf32(c[mt][nt], ahf[mt], bhf[nt]);
                    mma_tf32(c[mt][nt], ahf[mt], blf[nt]);
                    mma_tf32(c[mt][nt], alf[mt], bhf[nt]);
                }
        }
    }

    #pragma unroll
    for (int nt = 0; nt < 4; nt++) {
        int col = n0 + wn + nt * 8 + 2 * tk;
        float b0 = bias[col], b1 = bias[col + 1];
        #pragma unroll
        for (int mt = 0; mt < 4; mt++) {
            int row0 = m0 + wm + mt * 16 + g;
            float2 v0 = {c[mt][nt][0] + b0, c[mt][nt][1] + b1};
            float2 v1 = {c[mt][nt][2] + b0, c[mt][nt][3] + b1};
            __stcs((float2*)(C + (size_t)row0 * G4H + col), v0);
            __stcs((float2*)(C + (size_t)(row0 + 8) * G4H + col), v1);
        }
    }
}

// ---------------------------------------------------------------------------
// Stage h into A-fragment layout (fp16): af[(c*32+lane)*4 + r] uint32.
// ---------------------------------------------------------------------------
template <int NC>
__device__ __forceinline__ void stage_af(const float* __restrict__ src1,
                                         const float* __restrict__ src2,
                                         uint32_t* af) {
    const int tid = threadIdx.x;
    for (int i = tid; i < NC * 32; i += 512) {
        int c = i >> 5, lane = i & 31;
        int gr = lane >> 2, tc = lane & 3;
        int k0 = 16 * c + 2 * tc;
        const float* s = (NC == 32 || k0 < 512) ? (src1 + k0) : (src2 + k0 - 512);
        float2 f0 = *(const float2*)(s + gr * PROJ);
        float2 f1 = *(const float2*)(s + (gr + 8) * PROJ);
        float2 f2 = *(const float2*)(s + gr * PROJ + 8);
        float2 f3 = *(const float2*)(s + (gr + 8) * PROJ + 8);
        *(uint4*)(af + (size_t)i * 4) =
            make_uint4(h2u(f0), h2u(f1), h2u(f2), h2u(f3));
    }
}

// ---------------------------------------------------------------------------
// Gate phase via HMMA: layer1 weights from persistent smem, layer2 via
// pairwise LDG.128. xg loads hoisted above the MMA loops to hide DRAM latency.
// ---------------------------------------------------------------------------
template <bool DO1, bool DO2>
__device__ __forceinline__ void gate_mma(
    const uint32_t* af, const uint2* pb1s, float* zbuf1, float* zbuf2,
    const float* __restrict__ xg1p, const float* __restrict__ xg2p)
{
    const int w = threadIdx.x >> 5, lane = threadIdx.x & 31;
    const int gate = w >> 2, jj8 = (w & 3) << 3;
    const int gr = lane >> 2, tc = lane & 3;
    const int ntg = gate * 512 + blockIdx.x * 4 + (w & 3);

    const int jl = jj8 + 2 * tc;
    const int rowg = gate * HID + blockIdx.x * 32 + jl;

    // prefetch xg (DRAM stream) so its latency overlaps the MMA weight loads
    float2 x1a, x1b, x2a, x2b;
    if (DO1) {
        x1a = __ldcs((const float2*)(xg1p + (size_t)gr * G4H + rowg));
        x1b = __ldcs((const float2*)(xg1p + (size_t)(gr + 8) * G4H + rowg));
    }
    if (DO2) {
        x2a = __ldcs((const float2*)(xg2p + (size_t)gr * G4H + rowg));
        x2b = __ldcs((const float2*)(xg2p + (size_t)(gr + 8) * G4H + rowg));
    }

    float acc1[4] = {0.f, 0.f, 0.f, 0.f};
    float acc2[4] = {0.f, 0.f, 0.f, 0.f};

    if (DO2) {
        // pairwise uint4 loads: one LDG.128 covers two k-chunks
        const uint4* p4 = (const uint4*)(g_pb2 + (size_t)ntg * 2048) + lane;
        #pragma unroll 8
        for (int cp = 0; cp < 32; cp++) {
            uint4 bv = p4[(size_t)cp * 32];
            uint4 a0 = *(const uint4*)(af + (size_t)((2 * cp) * 32 + lane) * 4);
            uint4 a1 = *(const uint4*)(af + (size_t)((2 * cp + 1) * 32 + lane) * 4);
            uint32_t af0[4] = {a0.x, a0.y, a0.z, a0.w};
            uint32_t af1[4] = {a1.x, a1.y, a1.z, a1.w};
            uint32_t b0[2] = {bv.x, bv.y};
            uint32_t b1[2] = {bv.z, bv.w};
            mma_f16(acc2, af0, b0);
            mma_f16(acc2, af1, b1);
        }
    }
    if (DO1) {
        // layer-1 weights resident in shared memory
        const uint2* bp = pb1s + (size_t)w * 1024 + lane;
        #pragma unroll 8
        for (int c = 0; c < 32; c++) {
            uint4 av = *(const uint4*)(af + (size_t)(c * 32 + lane) * 4);
            uint2 bv = bp[(size_t)c * 32];
            uint32_t a[4] = {av.x, av.y, av.z, av.w};
            uint32_t b[2] = {bv.x, bv.y};
            mma_f16(acc1, a, b);
        }
    }

    if (DO1) {
        float2 z0 = {acc1[0] + x1a.x, acc1[1] + x1a.y};
        float2 z1 = {acc1[2] + x1b.x, acc1[3] + x1b.y};
        *(float2*)&zbuf1[gate * 512 + gr * 32 + jl] = z0;
        *(float2*)&zbuf1[gate * 512 + (gr + 8) * 32 + jl] = z1;
    }
    if (DO2) {
        float2 z0 = {acc2[0] + x2a.x, acc2[1] + x2a.y};
        float2 z1 = {acc2[2] + x2b.x, acc2[3] + x2b.y};
        *(float2*)&zbuf2[gate * 512 + gr * 32 + jl] = z0;
        *(float2*)&zbuf2[gate * 512 + (gr + 8) * 32 + jl] = z1;
    }
}

// ---------------------------------------------------------------------------
// Cell update for both layers (c-state in registers).
// ---------------------------------------------------------------------------
template <bool DO1, bool DO2>
__device__ __forceinline__ void cell_update(
    const float* zbuf1, const float* zbuf2,
    float& c1r, float& c2r, bool last1, bool last2)
{
    const int tid = threadIdx.x;
    const int b = tid >> 5, jl = tid & 31;
    const size_t off = (size_t)b * HID + blockIdx.x * 32 + jl;
    if (DO1) {
        float zi = zbuf1[0 * 512 + b * 32 + jl];
        float zf = zbuf1[1 * 512 + b * 32 + jl];
        float zg = zbuf1[2 * 512 + b * 32 + jl];
        float zo = zbuf1[3 * 512 + b * 32 + jl];
        float cn = sigf(zf) * c1r + sigf(zi) * tanhf(zg);
        c1r = cn;
        g_g1h[off] = sigf(zo) * tanhf(cn);
        if (last1) g_c1[off] = cn;
    }
    if (DO2) {
        float zi = zbuf2[0 * 512 + b * 32 + jl];
        float zf = zbuf2[1 * 512 + b * 32 + jl];
        float zg = zbuf2[2 * 512 + b * 32 + jl];
        float zo = zbuf2[3 * 512 + b * 32 + jl];
        float cn = sigf(zf) * c2r + sigf(zi) * tanhf(zg);
        c2r = cn;
        g_g2h[off] = sigf(zo) * tanhf(cn);
        if (last2) g_c2[off] = cn;
    }
}

// ---------------------------------------------------------------------------
// Proj staging + main loop + combined reduce (fp32 weights — exact proj).
// ---------------------------------------------------------------------------
__device__ __forceinline__ void stage_g(const float* __restrict__ gh,
                                        int kb, float* gpf) {
    const int tid = threadIdx.x;
    int bb = tid >> 7, k = tid & 127;
    int b0 = 4 * bb;
    float4 v;
    v.x = __ldcs(gh + (size_t)(b0 + 0) * HID + kb + k);
    v.y = __ldcs(gh + (size_t)(b0 + 1) * HID + kb + k);
    v.z = __ldcs(gh + (size_t)(b0 + 2) * HID + kb + k);
    v.w = __ldcs(gh + (size_t)(b0 + 3) * HID + kb + k);
    *(float4*)&gpf[k * HSTR + 4 * bb] = v;
}

__device__ __forceinline__ void proj_loop(
    const float* gpf, const float* __restrict__ Wtr,
    int p0, int kb, unsigned long long* predu)
{
    const int tid = threadIdx.x;
    const int ks = tid >> 7, r = tid & 127;
    const int rowg = r >> 2, bg = (r & 3) << 2;
    const int p4 = p0 + rowg * 4;
    const int kbeg = ks * 32;

    const ulonglong2* wp = (const ulonglong2*)(Wtr + (size_t)(kb + kbeg) * PROJ + p4);
    const float* hp = gpf + kbeg * HSTR + bg;

    unsigned long long acc[2][4];
    #pragma unroll
    for (int i = 0; i < 2; i++)
        #pragma unroll
        for (int j = 0; j < 4; j++) acc[i][j] = 0ull;

    #pragma unroll 8
    for (int k = 0; k < 32; k++) {
        ulonglong2 w = wp[(size_t)k * (PROJ / 4)];
        float4 h = *(const float4*)(hp + k * HSTR);
        unsigned long long h0 = pk2(h.x, h.x), h1 = pk2(h.y, h.y);
        unsigned long long h2 = pk2(h.z, h.z), h3 = pk2(h.w, h.w);
        fma2(acc[0][0], w.x, h0); fma2(acc[1][0], w.y, h0);
        fma2(acc[0][1], w.x, h1); fma2(acc[1][1], w.y, h1);
        fma2(acc[0][2], w.x, h2); fma2(acc[1][2], w.y, h2);
        fma2(acc[0][3], w.x, h3); fma2(acc[1][3], w.y, h3);
    }

    unsigned long long* dst = predu + (size_t)ks * 1152 + r * 9;
    #pragma unroll
    for (int rp = 0; rp < 2; rp++)
        #pragma unroll
        for (int bi = 0; bi < 4; bi++) dst[rp * 4 + bi] = acc[rp][bi];
}

template <bool DO1, bool DO2>
__device__ __forceinline__ void proj_reduce(
    float* __restrict__ hout1, float* __restrict__ hout2,
    const unsigned long long* predu1, const unsigned long long* predu2, int p0)
{
    const int t = threadIdx.x;
    const int layer = t >> 8;
    const int rr = (t >> 1) & 127;
    const int q = t & 1;
    if ((layer == 0 && !DO1) || (layer == 1 && !DO2)) return;

    const unsigned long long* predu = layer ? predu2 : predu1;
    float* hout = layer ? hout2 : hout1;
    const int rowg = rr >> 2, bg = (rr & 3) << 2;
    const int p4 = p0 + rowg * 4;

    #pragma unroll
    for (int bi = 0; bi < 4; bi++) {
        unsigned long long sum = predu[rr * 9 + q * 4 + bi];
        #pragma unroll
        for (int g = 1; g < 4; g++)
            sum = add2(sum, predu[(size_t)g * 1152 + rr * 9 + q * 4 + bi]);
        float2 v = up2(sum);
        float* o = hout + (size_t)(bg + bi) * PROJ + p4 + 2 * q;
        atomicAdd(o + 0, v.x);
        atomicAdd(o + 1, v.y);
    }
}

// ---------------------------------------------------------------------------
// Persistent recurrence: HMMA gates (layer1 weights in smem) + fp32 proj.
// ---------------------------------------------------------------------------
__global__ void __launch_bounds__(512, 1) recurrence_kernel() {
    extern __shared__ float smem[];
    uint2* pb1s = (uint2*)smem;                        // [0, 32768) floats
    uint32_t* af = (uint32_t*)(smem + SM_PH);          // [PH, PH+8192)
    float* zbuf1 = smem + SM_PH + 8192;
    float* zbuf2 = smem + SM_PH + 10240;
    float* gpf1 = smem + SM_PH;
    float* gpf2 = smem + SM_PH + 2560;
    unsigned long long* predu1 = (unsigned long long*)(smem + SM_PH + 5120);
    unsigned long long* predu2 = (unsigned long long*)(smem + SM_PH + 14336);

    const int pt = blockIdx.x & 3;
    const int kc = blockIdx.x >> 2;
    const int p0 = pt * 128, kb = kc * 128;

    unsigned gen = g_genv;
    float c1r = 0.f, c2r = 0.f;

    // one-time: load this block's layer-1 b-fragments into smem
    {
        const int tid = threadIdx.x;
        for (int i = tid; i < 16 * 32 * 32; i += 512) {
            int w = i >> 10, rest = i & 1023;
            int c = rest >> 5, lane = rest & 31;
            int nt = (w >> 2) * 512 + blockIdx.x * 4 + (w & 3);
            pb1s[i] = g_pb1[(size_t)(nt * 32 + c) * 32 + lane];
        }
    }
    __syncthreads();

    // ---- prologue: G1(0) ----
    stage_af<32>(g_out1, nullptr, af);
    __syncthreads();
    gate_mma<true, false>(af, pb1s, zbuf1, zbuf2, g_xg1, nullptr);
    __syncthreads();
    cell_update<true, false>(zbuf1, zbuf2, c1r, c2r, false, false);
    gsync(gen);
    // ---- P1(0) -> out1[1] ----
    stage_g(g_g1h, kb, gpf1);
    __syncthreads();
    proj_loop(gpf1, g_Wtr1, p0, kb, predu1);
    __syncthreads();
    proj_reduce<true, false>(g_out1 + (size_t)1 * (BATCH * PROJ), nullptr,
                             predu1, predu2, p0);
    gsync(gen);

    for (int t = 0; t < T_STEPS - 1; t++) {
        // fused gate phase: G1(t+1) + G2(t)
        stage_af<64>(g_out1 + (size_t)(t + 1) * (BATCH * PROJ),
                     g_out2 + (size_t)t * (BATCH * PROJ), af);
        __syncthreads();
        gate_mma<true, true>(af, pb1s, zbuf1, zbuf2,
                             g_xg1 + (size_t)(t + 1) * BATCH * G4H,
                             g_xg2 + (size_t)t * BATCH * G4H);
        __syncthreads();
        cell_update<true, true>(zbuf1, zbuf2, c1r, c2r,
                                (t + 1 == T_STEPS - 1), false);
        gsync(gen);
        // fused proj phase: P1(t+1) + P2(t)
        stage_g(g_g1h, kb, gpf1);
        stage_g(g_g2h, kb, gpf2);
        __syncthreads();
        proj_loop(gpf1, g_Wtr1, p0, kb, predu1);
        proj_loop(gpf2, g_Wtr2, p0, kb, predu2);
        __syncthreads();
        proj_reduce<true, true>(g_out1 + (size_t)(t + 2) * (BATCH * PROJ),
                                g_out2 + (size_t)(t + 1) * (BATCH * PROJ),
                                predu1, predu2, p0);
        gsync(gen);
    }

    // ---- tail: G2(255) | P2(255) ----
    {
        int t = T_STEPS - 1;
        stage_af<64>(g_out1 + (size_t)(t + 1) * (BATCH * PROJ),
                     g_out2 + (size_t)t * (BATCH * PROJ), af);
        __syncthreads();
        gate_mma<false, true>(af, pb1s, zbuf1, zbuf2, nullptr,
                              g_xg2 + (size_t)t * BATCH * G4H);
        __syncthreads();
        cell_update<false, true>(zbuf1, zbuf2, c1r, c2r, false, true);
        gsync(gen);
        stage_g(g_g2h, kb, gpf2);
        __syncthreads();
        proj_loop(gpf2, g_Wtr2, p0, kb, predu2);
        __syncthreads();
        proj_reduce<false, true>(nullptr,
                                 g_out2 + (size_t)(t + 1) * (BATCH * PROJ),
                                 predu1, predu2, p0);
    }
}

// ---------------------------------------------------------------------------
// Heads: one warp per packed token
// ---------------------------------------------------------------------------
__global__ void __launch_bounds__(512) heads_kernel(
    const float* __restrict__ Wp, const float* __restrict__ bp,
    const float* __restrict__ Wa, const float* __restrict__ ba,
    float* __restrict__ out, int total) {
    const int t = blockIdx.x;
    const int w = threadIdx.x >> 5;
    const int lane = threadIdx.x & 31;
    if (w >= g_counts[t]) return;
    const int b = w;
    const int tok = g_offsets[t] + b;

    const float* o1 = g_out1 + (size_t)(t + 1) * (BATCH * PROJ) + (size_t)b * PROJ;
    const float* o2 = g_out2 + (size_t)(t + 1) * (BATCH * PROJ) + (size_t)b * PROJ;
    float v[16];
    #pragma unroll
    for (int i = 0; i < 16; i++) v[i] = o1[lane + 32 * i] + o2[lane + 32 * i];

    __shared__ float sp[16][20];
    __shared__ float sa[16][20];
    #pragma unroll
    for (int o = 0; o < 20; o++) {
        float s1 = 0.f, s2 = 0.f;
        #pragma unroll
        for (int i = 0; i < 16; i++) {
            float x = v[i];
            s1 = fmaf(x, Wp[o * PROJ + lane + 32 * i], s1);
            s2 = fmaf(x, Wa[o * PROJ + lane + 32 * i], s2);
        }
        #pragma unroll
        for (int off = 16; off; off >>= 1) {
            s1 += __shfl_xor_sync(0xffffffffu, s1, off);
            s2 += __shfl_xor_sync(0xffffffffu, s2, off);
        }
        if (lane == 0) { sp[w][o] = s1 + bp[o]; sa[w][o] = s2 + ba[o]; }
    }
    __syncwarp();
    if (lane == 0) {
        float m = -1e30f;
        #pragma unroll
        for (int o = 0; o < 20; o++) m = fmaxf(m, sp[w][o]);
        float e[20], sum = 0.f;
        #pragma unroll
        for (int o = 0; o < 20; o++) { e[o] = expf(sp[w][o] - m); sum += e[o]; }
        float inv = 1.f / sum;
        float* aa = out + (size_t)total * 20;
        #pragma unroll
        for (int o = 0; o < 20; o++) {
            out[(size_t)tok * 20 + o] = e[o] * inv;
            aa[(size_t)tok * 20 + o]  = sa[w][o];
        }
    }
}

// ---------------------------------------------------------------------------
// Final states: h1, c1, h2, c2
// ---------------------------------------------------------------------------
__global__ void finalize_kernel(float* __restrict__ out, int total) {
    const size_t base = (size_t)total * 40;
    const int nH = BATCH * PROJ;
    const int nC = BATCH * HID;
    int idx = blockIdx.x * blockDim.x + threadIdx.x;
    if (idx >= 2 * (nH + nC)) return;
    float v;
    if (idx < nH)                v = g_out1[(size_t)T_STEPS * nH + idx];
    else if (idx < nH + nC)      v = g_c1[idx - nH];
    else if (idx < 2 * nH + nC)  v = g_out2[(size_t)T_STEPS * nH + (idx - nH - nC)];
    else                         v = g_c2[idx - 2 * nH - nC];
    out[base + idx] = v;
}

// ---------------------------------------------------------------------------
// Host launch
// ---------------------------------------------------------------------------
extern "C" void kernel_launch(void* const* d_in, const int* in_sizes, int n_in,
                              void* d_out, int out_size) {
    const float* uncon  = (const float*)d_in[0];
    const float* con    = (const float*)d_in[1];
    const int*   lens   = (const int*)d_in[2];
    const float* W_ih1  = (const float*)d_in[3];
    const float* b1     = (const float*)d_in[4];
    const float* W_hh1  = (const float*)d_in[5];
    const float* W_hr1  = (const float*)d_in[6];
    const float* W_ih2  = (const float*)d_in[7];
    const float* b2     = (const float*)d_in[8];
    const float* W_hh2  = (const float*)d_in[9];
    const float* W_hr2  = (const float*)d_in[10];
    const float* W_pssm = (const float*)d_in[11];
    const float* b_pssm = (const float*)d_in[12];
    const float* W_aa   = (const float*)d_in[13];
    const float* b_aa   = (const float*)d_in[14];
    float* out = (float*)d_out;

    const int total = (out_size - 2 * (BATCH * PROJ + BATCH * HID)) / 40;

    float *p_xg1, *p_xg2;
    cudaGetSymbolAddress((void**)&p_xg1, g_xg1);
    cudaGetSymbolAddress((void**)&p_xg2, g_xg2);

    cudaFuncSetAttribute(recurrence_kernel,
                         cudaFuncAttributeMaxDynamicSharedMemorySize, SM_TOTAL_B);

    // 1: fused prep (HMMA fragment pack + proj transposes + zero + counts)
    prep_kernel<<<10241, 256>>>(W_hh1, W_ih2, W_hh2, W_hr1, W_hr2, lens);
    // 2,3: Phase A on tensor cores (3xTF32)
    sgemm_tf32<<<dim3(G4H / 128, (T_STEPS * BATCH) / 128), 256>>>(
        uncon, W_ih1, b1, p_xg1, F1, F1, F1, 0);
    sgemm_tf32<<<dim3(G4H / 128, (T_STEPS * BATCH) / 128), 256>>>(
        con, W_ih2, b2, p_xg2, F2CON, F2CON, 1280, 512);
    // 4: persistent recurrence (HMMA gates; layer1 weights resident in smem)
    recurrence_kernel<<<NBLK, 512, SM_TOTAL_B>>>();
    // 5,6: heads + final states
    heads_kernel<<<T_STEPS, 512>>>(W_pssm, b_pssm, W_aa, b_aa, out, total);
    finalize_kernel<<<(2 * (BATCH * PROJ + BATCH * HID) + 255) / 256, 256>>>(out, total);
}

// round 15
// speedup vs baseline: 1.3976x; 1.3976x over previous
#include <cuda_runtime.h>
#include <cuda_fp16.h>
#include <math.h>
#include <stdint.h>

// ---------------------------------------------------------------------------
// Problem constants
// ---------------------------------------------------------------------------
#define T_STEPS 256
#define BATCH   16
#define HID     4096          // H
#define PROJ    512           // P
#define G4H     16384         // 4*H
#define F1      532
#define F2CON   768           // con_x features (1280-512)
#define NBLK    128           // persistent grid size
#define HSTR    20            // padded smem row stride (floats) for proj h tiles

// persistent-kernel dynamic smem (floats): (same layout as R13)
//  gate phase: af (uint32) [0, 8192) | zbuf1 [8192,10240) | zbuf2 [10240,12288)
//  proj phase: gpf1 [0,2560) | gpf2 [2560,5120) | predu1 [5120,14336) | predu2 [14336,23552)
#define SM_TOTAL_F 23552
#define SM_TOTAL_B (SM_TOTAL_F * 4)     // 94208

// ---------------------------------------------------------------------------
// Device scratch (static only — no cudaMalloc allowed)
// ---------------------------------------------------------------------------
__device__ float g_xg1[(size_t)T_STEPS * BATCH * G4H];   // 268 MB
__device__ float g_xg2[(size_t)T_STEPS * BATCH * G4H];   // 268 MB
// gate weights packed in m16n8k16 B-fragment order (fp16):
// pb[nt][c][lane] = uint2{ half2(W[n][k0],W[n][k0+1]), half2(W[n][k0+8],W[n][k0+9]) }
//   n = nt*8 + lane/4, k0 = 16c + 2*(lane%4)
__device__ uint2 g_pb1[(size_t)2048 * 32 * 32];          // 16 MB (L1: K=512)
__device__ uint2 g_pb2[(size_t)2048 * 64 * 32];          // 32 MB (L2: K=1024)
__device__ float g_Wtr1[(size_t)HID * PROJ];             // W_hr1^T [k][p] fp32 (8 MB)
__device__ float g_Wtr2[(size_t)HID * PROJ];
__device__ float g_out1[(size_t)(T_STEPS + 1) * BATCH * PROJ];
__device__ float g_out2[(size_t)(T_STEPS + 1) * BATCH * PROJ];
__device__ float g_c1[BATCH * HID];
__device__ float g_c2[BATCH * HID];
__device__ float g_g1h[BATCH * HID];
__device__ float g_g2h[BATCH * HID];
__device__ int   g_counts[T_STEPS];
__device__ int   g_offsets[T_STEPS + 1];

__device__ volatile unsigned g_genv;   // monotonic across replays
__device__ unsigned g_arrive;          // self-resetting

// ---------------------------------------------------------------------------
// packed f32x2 helpers (proj path)
// ---------------------------------------------------------------------------
__device__ __forceinline__ unsigned long long pk2(float x, float y) {
    unsigned long long d;
    asm("mov.b64 %0, {%1, %2};" : "=l"(d) : "f"(x), "f"(y));
    return d;
}
__device__ __forceinline__ void fma2(unsigned long long& a, unsigned long long b,
                                     unsigned long long c) {
    asm("fma.rn.f32x2 %0, %1, %2, %0;" : "+l"(a) : "l"(b), "l"(c));
}
__device__ __forceinline__ unsigned long long add2(unsigned long long a,
                                                   unsigned long long b) {
    unsigned long long d;
    asm("add.rn.f32x2 %0, %1, %2;" : "=l"(d) : "l"(a), "l"(b));
    return d;
}
__device__ __forceinline__ float2 up2(unsigned long long d) {
    float2 r;
    asm("mov.b64 {%0, %1}, %2;" : "=f"(r.x), "=f"(r.y) : "l"(d));
    return r;
}
__device__ __forceinline__ float sigf(float x) { return 1.f / (1.f + expf(-x)); }

__device__ __forceinline__ uint32_t h2u(float2 f) {
    __half2 h = __float22half2_rn(f);
    return *(uint32_t*)&h;
}
__device__ __forceinline__ float2 u2f(uint32_t u) {
    return __half22float2(*(__half2*)&u);
}

// ---------------------------------------------------------------------------
// fp16 HMMA m16n8k16 (fp32 accumulate)
// ---------------------------------------------------------------------------
__device__ __forceinline__ void mma_f16(float c[4], const uint32_t a[4],
                                        const uint32_t b[2]) {
    asm volatile(
        "mma.sync.aligned.m16n8k16.row.col.f32.f16.f16.f32 "
        "{%0,%1,%2,%3}, {%4,%5,%6,%7}, {%8,%9}, {%0,%1,%2,%3};\n"
        : "+f"(c[0]), "+f"(c[1]), "+f"(c[2]), "+f"(c[3])
        : "r"(a[0]), "r"(a[1]), "r"(a[2]), "r"(a[3]), "r"(b[0]), "r"(b[1]));
}

// ---------------------------------------------------------------------------
// grid-wide barrier
// ---------------------------------------------------------------------------
__device__ __forceinline__ void gsync(unsigned& gen) {
    __syncthreads();
    if (threadIdx.x == 0) {
        unsigned next = gen + 1;
        __threadfence();
        if (atomicAdd(&g_arrive, 1u) == (unsigned)(NBLK - 1)) {
            g_arrive = 0u;
            __threadfence();
            g_genv = next;
        } else {
            while (g_genv != next) {}
            __threadfence();
        }
        gen = next;
    }
    __syncthreads();
}

// ---------------------------------------------------------------------------
// Fused prep: pack gate weights into HMMA fragment order (fp16),
// transpose proj weights (fp32), zero states, packed-seq counts.
// blocks: [0,2048) pb1 | [2048,4096) pb2 | [4096,6144) Wtr1 | [6144,8192) Wtr2
//         8192 counts | (8192,10241) zero
// ---------------------------------------------------------------------------
__global__ void prep_kernel(const float* __restrict__ W_hh1,
                            const float* __restrict__ W_ih2,
                            const float* __restrict__ W_hh2,
                            const float* __restrict__ W_hr1,
                            const float* __restrict__ W_hr2,
                            const int* __restrict__ lens) {
    int bid = blockIdx.x;
    int tid = threadIdx.x;
    if (bid < 2048) {                       // pb1: nt = bid, 32 chunks
        int nt = bid;
        #pragma unroll
        for (int j = 0; j < 4; j++) {
            int i = tid + j * 256;          // 0..1023
            int c = i >> 5, lane = i & 31;
            int gr = lane >> 2, tc = lane & 3;
            int n = nt * 8 + gr;
            int k0 = 16 * c + 2 * tc;
            const float* src = W_hh1 + (size_t)n * 512;
            float2 f0 = *(const float2*)(src + k0);
            float2 f1 = *(const float2*)(src + k0 + 8);
            g_pb1[(size_t)(nt * 32 + c) * 32 + lane] = make_uint2(h2u(f0), h2u(f1));
        }
    } else if (bid < 4096) {                // pb2: nt = bid-2048, 64 chunks
        int nt = bid - 2048;
        #pragma unroll
        for (int j = 0; j < 8; j++) {
            int i = tid + j * 256;          // 0..2047
            int c = i >> 5, lane = i & 31;
            int gr = lane >> 2, tc = lane & 3;
            int n = nt * 8 + gr;
            int k0 = 16 * c + 2 * tc;
            const float* src = (c < 32) ? (W_ih2 + (size_t)n * 1280 + k0)
                                        : (W_hh2 + (size_t)n * 512 + (k0 - 512));
            float2 f0 = *(const float2*)src;
            float2 f1 = *(const float2*)(src + 8);
            g_pb2[(size_t)(nt * 64 + c) * 32 + lane] = make_uint2(h2u(f0), h2u(f1));
        }
    } else if (bid < 8192) {                // proj transposes (32x33 tiles)
        __shared__ float tile[32][33];
        const float* in;
        float* out;
        int tix;
        if (bid < 6144) { in = W_hr1; out = g_Wtr1; tix = bid - 4096; }
        else            { in = W_hr2; out = g_Wtr2; tix = bid - 6144; }
        const int rows = 512, ldin = HID;
        int nbx = rows >> 5;                // 16
        int bx = tix % nbx, by = tix / nbx;
        int j0 = bx * 32, k0 = by * 32;
        int tx = tid & 31, ty = tid >> 5;
        #pragma unroll
        for (int i = 0; i < 32; i += 8) {
            int j = j0 + ty + i, k = k0 + tx;
            tile[ty + i][tx] = in[(size_t)j * ldin + k];
        }
        __syncthreads();
        #pragma unroll
        for (int i = 0; i < 32; i += 8) {
            int k = k0 + ty + i, j = j0 + tx;
            out[(size_t)k * rows + j] = tile[tx][ty + i];
        }
    } else if (bid == 8192) {               // counts
        int t = tid;
        int c = 0;
        #pragma unroll
        for (int b = 0; b < BATCH; b++) c += (lens[b] > t) ? 1 : 0;
        g_counts[t] = c;
        __syncthreads();
        if (t == 0) {
            int s = 0;
            for (int i = 0; i < T_STEPS; i++) { g_offsets[i] = s; s += g_counts[i]; }
            g_offsets[T_STEPS] = s;
        }
    } else {                                // zero
        const size_t n1 = (size_t)(T_STEPS + 1) * BATCH * PROJ;
        const size_t nc = (size_t)BATCH * HID;
        const size_t tot = 2 * n1 + 2 * nc;
        size_t base = (size_t)(bid - 8193) * 256 + tid;
        for (size_t i = base; i < tot; i += (size_t)2048 * 256) {
            if (i < n1)               g_out1[i] = 0.f;
            else if (i < 2 * n1)      g_out2[i - n1] = 0.f;
            else if (i < 2 * n1 + nc) g_c1[i - 2 * n1] = 0.f;
            else                      g_c2[i - 2 * n1 - nc] = 0.f;
        }
    }
}

// ---------------------------------------------------------------------------
// Phase A GEMM on tensor cores: 3xFP16 split HMMA (fp32-grade accuracy).
// C[m][n] = A[m]·B[n] + bias[n]; A [M][lda], B [N][ldb] row-major (NT GEMM).
// Block tile 128x128, 8 warps = 2(m)x4(n), warp 64x32 via m16n8k16, K-slab 16.
// ---------------------------------------------------------------------------
__global__ void __launch_bounds__(256)
sgemm_f16(const float* __restrict__ A, const float* __restrict__ B,
          const float* __restrict__ bias, float* __restrict__ C,
          int K, int lda, int ldb, int boff) {
    __shared__ uint4 afh[256], afl[256];     // M side: 8 mt x 32 lanes
    __shared__ uint2 bfh[512], bfl[512];     // N side: 16 nt x 32 lanes

    const int tid = threadIdx.x;
    const int m0 = blockIdx.y * 128, n0 = blockIdx.x * 128;
    const int warp = tid >> 5, lane = tid & 31;
    const int mtb = (warp >> 2) * 4;   // m-frag base (0 or 4)
    const int ntb = (warp & 3) * 4;    // n-frag base (0..12)
    const int g  = lane >> 2;          // 0..7
    const int tk = lane & 3;           // 0..3

    float c[4][4][4];
    #pragma unroll
    for (int mt = 0; mt < 4; mt++)
        #pragma unroll
        for (int nt = 0; nt < 4; nt++)
            #pragma unroll
            for (int i = 0; i < 4; i++) c[mt][nt][i] = 0.f;

    for (int k0 = 0; k0 < K; k0 += 16) {
        __syncthreads();   // protect smem from previous slab's readers
        // ---- stage A fragments (hi/lo): entry = (mt, lane), one per thread ----
        {
            int mt = tid >> 5, ln = tid & 31;
            int gr = ln >> 2, tc = ln & 3;
            int r0 = m0 + mt * 16 + gr;
            int ca = k0 + 2 * tc, cb = ca + 8;
            float2 fa0 = (ca < K) ? *(const float2*)(A + (size_t)r0 * lda + ca)
                                  : make_float2(0.f, 0.f);
            float2 fa1 = (ca < K) ? *(const float2*)(A + (size_t)(r0 + 8) * lda + ca)
                                  : make_float2(0.f, 0.f);
            float2 fa2 = (cb < K) ? *(const float2*)(A + (size_t)r0 * lda + cb)
                                  : make_float2(0.f, 0.f);
            float2 fa3 = (cb < K) ? *(const float2*)(A + (size_t)(r0 + 8) * lda + cb)
                                  : make_float2(0.f, 0.f);
            uint32_t h0 = h2u(fa0), h1 = h2u(fa1), h2 = h2u(fa2), h3 = h2u(fa3);
            float2 d0 = u2f(h0), d1 = u2f(h1), d2 = u2f(h2), d3 = u2f(h3);
            uint32_t l0 = h2u(make_float2(fa0.x - d0.x, fa0.y - d0.y));
            uint32_t l1 = h2u(make_float2(fa1.x - d1.x, fa1.y - d1.y));
            uint32_t l2 = h2u(make_float2(fa2.x - d2.x, fa2.y - d2.y));
            uint32_t l3 = h2u(make_float2(fa3.x - d3.x, fa3.y - d3.y));
            afh[tid] = make_uint4(h0, h1, h2, h3);
            afl[tid] = make_uint4(l0, l1, l2, l3);
        }
        // ---- stage B fragments (hi/lo): 2 entries per thread ----
        #pragma unroll
        for (int e = 0; e < 2; e++) {
            int i = tid + e * 256;
            int nt = i >> 5, ln = i & 31;
            int gr = ln >> 2, tc = ln & 3;
            int n = n0 + nt * 8 + gr;
            int ca = k0 + 2 * tc, cb = ca + 8;
            float2 f0 = (ca < K) ? *(const float2*)(B + (size_t)n * ldb + boff + ca)
                                 : make_float2(0.f, 0.f);
            float2 f1 = (cb < K) ? *(const float2*)(B + (size_t)n * ldb + boff + cb)
                                 : make_float2(0.f, 0.f);
            uint32_t h0 = h2u(f0), h1 = h2u(f1);
            float2 d0 = u2f(h0), d1 = u2f(h1);
            uint32_t l0 = h2u(make_float2(f0.x - d0.x, f0.y - d0.y));
            uint32_t l1 = h2u(make_float2(f1.x - d1.x, f1.y - d1.y));
            bfh[i] = make_uint2(h0, h1);
            bfl[i] = make_uint2(l0, l1);
        }
        __syncthreads();

        // ---- compute: 4x4 frags x 3 terms ----
        uint32_t ah[4][4], al[4][4], bh[4][2], bl[4][2];
        #pragma unroll
        for (int mt = 0; mt < 4; mt++) {
            uint4 vh = afh[(mtb + mt) * 32 + lane];
            uint4 vl = afl[(mtb + mt) * 32 + lane];
            ah[mt][0] = vh.x; ah[mt][1] = vh.y; ah[mt][2] = vh.z; ah[mt][3] = vh.w;
            al[mt][0] = vl.x; al[mt][1] = vl.y; al[mt][2] = vl.z; al[mt][3] = vl.w;
        }
        #pragma unroll
        for (int nt = 0; nt < 4; nt++) {
            uint2 vh = bfh[(ntb + nt) * 32 + lane];
            uint2 vl = bfl[(ntb + nt) * 32 + lane];
            bh[nt][0] = vh.x; bh[nt][1] = vh.y;
            bl[nt][0] = vl.x; bl[nt][1] = vl.y;
        }
        #pragma unroll
        for (int mt = 0; mt < 4; mt++)
            #pragma unroll
            for (int nt = 0; nt < 4; nt++) {
                mma_f16(c[mt][nt], ah[mt], bh[nt]);   // hi*hi
                mma_f16(c[mt][nt], ah[mt], bl[nt]);   // hi*lo
                mma_f16(c[mt][nt], al[mt], bh[nt]);   // lo*hi
            }
    }

    // epilogue: add bias, streaming stores
    #pragma unroll
    for (int nt = 0; nt < 4; nt++) {
        int col = n0 + (ntb + nt) * 8 + 2 * tk;
        float b0 = bias[col], b1 = bias[col + 1];
        #pragma unroll
        for (int mt = 0; mt < 4; mt++) {
            int row0 = m0 + (mtb + mt) * 16 + g;
            float2 v0 = {c[mt][nt][0] + b0, c[mt][nt][1] + b1};
            float2 v1 = {c[mt][nt][2] + b0, c[mt][nt][3] + b1};
            __stcs((float2*)(C + (size_t)row0 * G4H + col), v0);
            __stcs((float2*)(C + (size_t)(row0 + 8) * G4H + col), v1);
        }
    }
}

// ---------------------------------------------------------------------------
// Stage h into A-fragment layout (fp16): af[(c*32+lane)*4 + r] uint32.
// k<512 from src1 (h1), else src2 (h2). NC = number of 16-k chunks.
// ---------------------------------------------------------------------------
template <int NC>
__device__ __forceinline__ void stage_af(const float* __restrict__ src1,
                                         const float* __restrict__ src2,
                                         uint32_t* af) {
    const int tid = threadIdx.x;
    for (int i = tid; i < NC * 32; i += 512) {
        int c = i >> 5, lane = i & 31;
        int gr = lane >> 2, tc = lane & 3;
        int k0 = 16 * c + 2 * tc;
        const float* s = (NC == 32 || k0 < 512) ? (src1 + k0) : (src2 + k0 - 512);
        float2 f0 = *(const float2*)(s + gr * PROJ);
        float2 f1 = *(const float2*)(s + (gr + 8) * PROJ);
        float2 f2 = *(const float2*)(s + gr * PROJ + 8);
        float2 f3 = *(const float2*)(s + (gr + 8) * PROJ + 8);
        *(uint4*)(af + (size_t)i * 4) =
            make_uint4(h2u(f0), h2u(f1), h2u(f2), h2u(f3));
    }
}

// ---------------------------------------------------------------------------
// Gate phase via HMMA: 16 warps, each owns one 8-row N-tile per layer,
// full-K accumulation. z = acc + xg -> zbuf.
// ---------------------------------------------------------------------------
template <bool DO1, bool DO2>
__device__ __forceinline__ void gate_mma(
    const uint32_t* af, float* zbuf1, float* zbuf2,
    const float* __restrict__ xg1p, const float* __restrict__ xg2p)
{
    const int w = threadIdx.x >> 5, lane = threadIdx.x & 31;
    const int gate = w >> 2, jj8 = (w & 3) << 3;
    const int gr = lane >> 2, tc = lane & 3;
    const int ntg = gate * 512 + blockIdx.x * 4 + (w & 3);

    float acc1[4] = {0.f, 0.f, 0.f, 0.f};
    float acc2[4] = {0.f, 0.f, 0.f, 0.f};

    if (DO1) {
        const uint2* bp = g_pb1 + (size_t)ntg * 32 * 32 + lane;
        #pragma unroll 8
        for (int c = 0; c < 32; c++) {
            uint4 av = *(const uint4*)(af + (size_t)(c * 32 + lane) * 4);
            uint2 bv = bp[(size_t)c * 32];
            uint32_t a[4] = {av.x, av.y, av.z, av.w};
            uint32_t b[2] = {bv.x, bv.y};
            mma_f16(acc1, a, b);
        }
    }
    if (DO2) {
        const uint2* bp = g_pb2 + (size_t)ntg * 64 * 32 + lane;
        #pragma unroll 8
        for (int c = 0; c < 64; c++) {
            uint4 av = *(const uint4*)(af + (size_t)(c * 32 + lane) * 4);
            uint2 bv = bp[(size_t)c * 32];
            uint32_t a[4] = {av.x, av.y, av.z, av.w};
            uint32_t b[2] = {bv.x, bv.y};
            mma_f16(acc2, a, b);
        }
    }

    const int jl = jj8 + 2 * tc;
    const int rowg = gate * HID + blockIdx.x * 32 + jl;
    if (DO1) {
        float2 x0 = __ldcs((const float2*)(xg1p + (size_t)gr * G4H + rowg));
        float2 x1 = __ldcs((const float2*)(xg1p + (size_t)(gr + 8) * G4H + rowg));
        float2 z0 = {acc1[0] + x0.x, acc1[1] + x0.y};
        float2 z1 = {acc1[2] + x1.x, acc1[3] + x1.y};
        *(float2*)&zbuf1[gate * 512 + gr * 32 + jl] = z0;
        *(float2*)&zbuf1[gate * 512 + (gr + 8) * 32 + jl] = z1;
    }
    if (DO2) {
        float2 x0 = __ldcs((const float2*)(xg2p + (size_t)gr * G4H + rowg));
        float2 x1 = __ldcs((const float2*)(xg2p + (size_t)(gr + 8) * G4H + rowg));
        float2 z0 = {acc2[0] + x0.x, acc2[1] + x0.y};
        float2 z1 = {acc2[2] + x1.x, acc2[3] + x1.y};
        *(float2*)&zbuf2[gate * 512 + gr * 32 + jl] = z0;
        *(float2*)&zbuf2[gate * 512 + (gr + 8) * 32 + jl] = z1;
    }
}

// ---------------------------------------------------------------------------
// Cell update for both layers (c-state in registers).
// ---------------------------------------------------------------------------
template <bool DO1, bool DO2>
__device__ __forceinline__ void cell_update(
    const float* zbuf1, const float* zbuf2,
    float& c1r, float& c2r, bool last1, bool last2)
{
    const int tid = threadIdx.x;
    const int b = tid >> 5, jl = tid & 31;
    const size_t off = (size_t)b * HID + blockIdx.x * 32 + jl;
    if (DO1) {
        float zi = zbuf1[0 * 512 + b * 32 + jl];
        float zf = zbuf1[1 * 512 + b * 32 + jl];
        float zg = zbuf1[2 * 512 + b * 32 + jl];
        float zo = zbuf1[3 * 512 + b * 32 + jl];
        float cn = sigf(zf) * c1r + sigf(zi) * tanhf(zg);
        c1r = cn;
        g_g1h[off] = sigf(zo) * tanhf(cn);
        if (last1) g_c1[off] = cn;
    }
    if (DO2) {
        float zi = zbuf2[0 * 512 + b * 32 + jl];
        float zf = zbuf2[1 * 512 + b * 32 + jl];
        float zg = zbuf2[2 * 512 + b * 32 + jl];
        float zo = zbuf2[3 * 512 + b * 32 + jl];
        float cn = sigf(zf) * c2r + sigf(zi) * tanhf(zg);
        c2r = cn;
        g_g2h[off] = sigf(zo) * tanhf(cn);
        if (last2) g_c2[off] = cn;
    }
}

// ---------------------------------------------------------------------------
// Proj staging + main loop + combined reduce (fp32 weights — exact proj).
// ---------------------------------------------------------------------------
__device__ __forceinline__ void stage_g(const float* __restrict__ gh,
                                        int kb, float* gpf) {
    const int tid = threadIdx.x;
    int bb = tid >> 7, k = tid & 127;
    int b0 = 4 * bb;
    float4 v;
    v.x = __ldcs(gh + (size_t)(b0 + 0) * HID + kb + k);
    v.y = __ldcs(gh + (size_t)(b0 + 1) * HID + kb + k);
    v.z = __ldcs(gh + (size_t)(b0 + 2) * HID + kb + k);
    v.w = __ldcs(gh + (size_t)(b0 + 3) * HID + kb + k);
    *(float4*)&gpf[k * HSTR + 4 * bb] = v;
}

__device__ __forceinline__ void proj_loop(
    const float* gpf, const float* __restrict__ Wtr,
    int p0, int kb, unsigned long long* predu)
{
    const int tid = threadIdx.x;
    const int ks = tid >> 7, r = tid & 127;
    const int rowg = r >> 2, bg = (r & 3) << 2;
    const int p4 = p0 + rowg * 4;
    const int kbeg = ks * 32;

    const ulonglong2* wp = (const ulonglong2*)(Wtr + (size_t)(kb + kbeg) * PROJ + p4);
    const float* hp = gpf + kbeg * HSTR + bg;

    unsigned long long acc[2][4];
    #pragma unroll
    for (int i = 0; i < 2; i++)
        #pragma unroll
        for (int j = 0; j < 4; j++) acc[i][j] = 0ull;

    #pragma unroll 8
    for (int k = 0; k < 32; k++) {
        ulonglong2 w = wp[(size_t)k * (PROJ / 4)];
        float4 h = *(const float4*)(hp + k * HSTR);
        unsigned long long h0 = pk2(h.x, h.x), h1 = pk2(h.y, h.y);
        unsigned long long h2 = pk2(h.z, h.z), h3 = pk2(h.w, h.w);
        fma2(acc[0][0], w.x, h0); fma2(acc[1][0], w.y, h0);
        fma2(acc[0][1], w.x, h1); fma2(acc[1][1], w.y, h1);
        fma2(acc[0][2], w.x, h2); fma2(acc[1][2], w.y, h2);
        fma2(acc[0][3], w.x, h3); fma2(acc[1][3], w.y, h3);
    }

    unsigned long long* dst = predu + (size_t)ks * 1152 + r * 9;
    #pragma unroll
    for (int rp = 0; rp < 2; rp++)
        #pragma unroll
        for (int bi = 0; bi < 4; bi++) dst[rp * 4 + bi] = acc[rp][bi];
}

template <bool DO1, bool DO2>
__device__ __forceinline__ void proj_reduce(
    float* __restrict__ hout1, float* __restrict__ hout2,
    const unsigned long long* predu1, const unsigned long long* predu2, int p0)
{
    const int t = threadIdx.x;
    const int layer = t >> 8;
    const int rr = (t >> 1) & 127;
    const int q = t & 1;
    if ((layer == 0 && !DO1) || (layer == 1 && !DO2)) return;

    const unsigned long long* predu = layer ? predu2 : predu1;
    float* hout = layer ? hout2 : hout1;
    const int rowg = rr >> 2, bg = (rr & 3) << 2;
    const int p4 = p0 + rowg * 4;

    #pragma unroll
    for (int bi = 0; bi < 4; bi++) {
        unsigned long long sum = predu[rr * 9 + q * 4 + bi];
        #pragma unroll
        for (int g = 1; g < 4; g++)
            sum = add2(sum, predu[(size_t)g * 1152 + rr * 9 + q * 4 + bi]);
        float2 v = up2(sum);
        float* o = hout + (size_t)(bg + bi) * PROJ + p4 + 2 * q;
        atomicAdd(o + 0, v.x);
        atomicAdd(o + 1, v.y);
    }
}

// ---------------------------------------------------------------------------
// Persistent recurrence: HMMA gates + fp32 proj, fused dual-layer phases.
// ---------------------------------------------------------------------------
__global__ void __launch_bounds__(512, 1) recurrence_kernel() {
    extern __shared__ float smem[];
    uint32_t* af = (uint32_t*)smem;                  // [0, 8192) uint32
    float* zbuf1 = smem + 8192;
    float* zbuf2 = smem + 10240;
    float* gpf1 = smem;
    float* gpf2 = smem + 2560;
    unsigned long long* predu1 = (unsigned long long*)(smem + 5120);
    unsigned long long* predu2 = (unsigned long long*)(smem + 14336);

    const int pt = blockIdx.x & 3;
    const int kc = blockIdx.x >> 2;
    const int p0 = pt * 128, kb = kc * 128;

    unsigned gen = g_genv;
    float c1r = 0.f, c2r = 0.f;

    // ---- prologue: G1(0) ----
    stage_af<32>(g_out1, nullptr, af);
    __syncthreads();
    gate_mma<true, false>(af, zbuf1, zbuf2, g_xg1, nullptr);
    __syncthreads();
    cell_update<true, false>(zbuf1, zbuf2, c1r, c2r, false, false);
    gsync(gen);
    // ---- P1(0) -> out1[1] ----
    stage_g(g_g1h, kb, gpf1);
    __syncthreads();
    proj_loop(gpf1, g_Wtr1, p0, kb, predu1);
    __syncthreads();
    proj_reduce<true, false>(g_out1 + (size_t)1 * (BATCH * PROJ), nullptr,
                             predu1, predu2, p0);
    gsync(gen);

    for (int t = 0; t < T_STEPS - 1; t++) {
        // fused gate phase: G1(t+1) + G2(t)
        stage_af<64>(g_out1 + (size_t)(t + 1) * (BATCH * PROJ),
                     g_out2 + (size_t)t * (BATCH * PROJ), af);
        __syncthreads();
        gate_mma<true, true>(af, zbuf1, zbuf2,
                             g_xg1 + (size_t)(t + 1) * BATCH * G4H,
                             g_xg2 + (size_t)t * BATCH * G4H);
        __syncthreads();
        cell_update<true, true>(zbuf1, zbuf2, c1r, c2r,
                                (t + 1 == T_STEPS - 1), false);
        gsync(gen);
        // fused proj phase: P1(t+1) + P2(t)
        stage_g(g_g1h, kb, gpf1);
        stage_g(g_g2h, kb, gpf2);
        __syncthreads();
        proj_loop(gpf1, g_Wtr1, p0, kb, predu1);
        proj_loop(gpf2, g_Wtr2, p0, kb, predu2);
        __syncthreads();
        proj_reduce<true, true>(g_out1 + (size_t)(t + 2) * (BATCH * PROJ),
                                g_out2 + (size_t)(t + 1) * (BATCH * PROJ),
                                predu1, predu2, p0);
        gsync(gen);
    }

    // ---- tail: G2(255) | P2(255) ----
    {
        int t = T_STEPS - 1;
        stage_af<64>(g_out1 + (size_t)(t + 1) * (BATCH * PROJ),
                     g_out2 + (size_t)t * (BATCH * PROJ), af);
        __syncthreads();
        gate_mma<false, true>(af, zbuf1, zbuf2, nullptr,
                              g_xg2 + (size_t)t * BATCH * G4H);
        __syncthreads();
        cell_update<false, true>(zbuf1, zbuf2, c1r, c2r, false, true);
        gsync(gen);
        stage_g(g_g2h, kb, gpf2);
        __syncthreads();
        proj_loop(gpf2, g_Wtr2, p0, kb, predu2);
        __syncthreads();
        proj_reduce<false, true>(nullptr,
                                 g_out2 + (size_t)(t + 1) * (BATCH * PROJ),
                                 predu1, predu2, p0);
    }
}

// ---------------------------------------------------------------------------
// Heads: one warp per packed token
// ---------------------------------------------------------------------------
__global__ void __launch_bounds__(512) heads_kernel(
    const float* __restrict__ Wp, const float* __restrict__ bp,
    const float* __restrict__ Wa, const float* __restrict__ ba,
    float* __restrict__ out, int total) {
    const int t = blockIdx.x;
    const int w = threadIdx.x >> 5;
    const int lane = threadIdx.x & 31;
    if (w >= g_counts[t]) return;
    const int b = w;
    const int tok = g_offsets[t] + b;

    const float* o1 = g_out1 + (size_t)(t + 1) * (BATCH * PROJ) + (size_t)b * PROJ;
    const float* o2 = g_out2 + (size_t)(t + 1) * (BATCH * PROJ) + (size_t)b * PROJ;
    float v[16];
    #pragma unroll
    for (int i = 0; i < 16; i++) v[i] = o1[lane + 32 * i] + o2[lane + 32 * i];

    __shared__ float sp[16][20];
    __shared__ float sa[16][20];
    #pragma unroll
    for (int o = 0; o < 20; o++) {
        float s1 = 0.f, s2 = 0.f;
        #pragma unroll
        for (int i = 0; i < 16; i++) {
            float x = v[i];
            s1 = fmaf(x, Wp[o * PROJ + lane + 32 * i], s1);
            s2 = fmaf(x, Wa[o * PROJ + lane + 32 * i], s2);
        }
        #pragma unroll
        for (int off = 16; off; off >>= 1) {
            s1 += __shfl_xor_sync(0xffffffffu, s1, off);
            s2 += __shfl_xor_sync(0xffffffffu, s2, off);
        }
        if (lane == 0) { sp[w][o] = s1 + bp[o]; sa[w][o] = s2 + ba[o]; }
    }
    __syncwarp();
    if (lane == 0) {
        float m = -1e30f;
        #pragma unroll
        for (int o = 0; o < 20; o++) m = fmaxf(m, sp[w][o]);
        float e[20], sum = 0.f;
        #pragma unroll
        for (int o = 0; o < 20; o++) { e[o] = expf(sp[w][o] - m); sum += e[o]; }
        float inv = 1.f / sum;
        float* aa = out + (size_t)total * 20;
        #pragma unroll
        for (int o = 0; o < 20; o++) {
            out[(size_t)tok * 20 + o] = e[o] * inv;
            aa[(size_t)tok * 20 + o]  = sa[w][o];
        }
    }
}

// ---------------------------------------------------------------------------
// Final states: h1, c1, h2, c2
// ---------------------------------------------------------------------------
__global__ void finalize_kernel(float* __restrict__ out, int total) {
    const size_t base = (size_t)total * 40;
    const int nH = BATCH * PROJ;
    const int nC = BATCH * HID;
    int idx = blockIdx.x * blockDim.x + threadIdx.x;
    if (idx >= 2 * (nH + nC)) return;
    float v;
    if (idx < nH)                v = g_out1[(size_t)T_STEPS * nH + idx];
    else if (idx < nH + nC)      v = g_c1[idx - nH];
    else if (idx < 2 * nH + nC)  v = g_out2[(size_t)T_STEPS * nH + (idx - nH - nC)];
    else                         v = g_c2[idx - 2 * nH - nC];
    out[base + idx] = v;
}

// ---------------------------------------------------------------------------
// Host launch
// ---------------------------------------------------------------------------
extern "C" void kernel_launch(void* const* d_in, const int* in_sizes, int n_in,
                              void* d_out, int out_size) {
    const float* uncon  = (const float*)d_in[0];
    const float* con    = (const float*)d_in[1];
    const int*   lens   = (const int*)d_in[2];
    const float* W_ih1  = (const float*)d_in[3];
    const float* b1     = (const float*)d_in[4];
    const float* W_hh1  = (const float*)d_in[5];
    const float* W_hr1  = (const float*)d_in[6];
    const float* W_ih2  = (const float*)d_in[7];
    const float* b2     = (const float*)d_in[8];
    const float* W_hh2  = (const float*)d_in[9];
    const float* W_hr2  = (const float*)d_in[10];
    const float* W_pssm = (const float*)d_in[11];
    const float* b_pssm = (const float*)d_in[12];
    const float* W_aa   = (const float*)d_in[13];
    const float* b_aa   = (const float*)d_in[14];
    float* out = (float*)d_out;

    const int total = (out_size - 2 * (BATCH * PROJ + BATCH * HID)) / 40;

    float *p_xg1, *p_xg2;
    cudaGetSymbolAddress((void**)&p_xg1, g_xg1);
    cudaGetSymbolAddress((void**)&p_xg2, g_xg2);

    cudaFuncSetAttribute(recurrence_kernel,
                         cudaFuncAttributeMaxDynamicSharedMemorySize, SM_TOTAL_B);

    // 1: fused prep (HMMA fragment pack + proj transposes + zero + counts)
    prep_kernel<<<10241, 256>>>(W_hh1, W_ih2, W_hh2, W_hr1, W_hr2, lens);
    // 2,3: Phase A on tensor cores (3xFP16 split HMMA)
    sgemm_f16<<<dim3(G4H / 128, (T_STEPS * BATCH) / 128), 256>>>(
        uncon, W_ih1, b1, p_xg1, F1, F1, F1, 0);
    sgemm_f16<<<dim3(G4H / 128, (T_STEPS * BATCH) / 128), 256>>>(
        con, W_ih2, b2, p_xg2, F2CON, F2CON, 1280, 512);
    // 4: persistent recurrence (HMMA gates, L2-resident fp16 weights)
    recurrence_kernel<<<NBLK, 512, SM_TOTAL_B>>>();
    // 5,6: heads + final states
    heads_kernel<<<T_STEPS, 512>>>(W_pssm, b_pssm, W_aa, b_aa, out, total);
    finalize_kernel<<<(2 * (BATCH * PROJ + BATCH * HID) + 255) / 256, 256>>>(out, total);
}

// round 16
// speedup vs baseline: 1.6268x; 1.1640x over previous
#include <cuda_runtime.h>
#include <cuda_fp16.h>
#include <math.h>
#include <stdint.h>

// ---------------------------------------------------------------------------
// Problem constants
// ---------------------------------------------------------------------------
#define T_STEPS 256
#define BATCH   16
#define HID     4096          // H
#define PROJ    512           // P
#define G4H     16384         // 4*H
#define F1      532
#define F2CON   768           // con_x features (1280-512)
#define NBLK    128           // persistent grid size

// persistent-kernel dynamic smem (floats):
//  gate: af (uint32) [0, 8192) | zbuf1 [8192,10240) | zbuf2 [10240,12288)
//  proj: paf1 (uint32) [0,1024) | paf2 [1024,2048)   (aliases af)
#define SM_TOTAL_F 12288
#define SM_TOTAL_B (SM_TOTAL_F * 4)     // 49152

// ---------------------------------------------------------------------------
// Device scratch (static only — no cudaMalloc allowed)
// ---------------------------------------------------------------------------
__device__ float g_xg1[(size_t)T_STEPS * BATCH * G4H];   // 268 MB
__device__ float g_xg2[(size_t)T_STEPS * BATCH * G4H];   // 268 MB
// gate weights packed in m16n8k16 B-fragment order (fp16):
// pb[nt][c][lane] = uint2{ half2(W[n][k0],W[n][k0+1]), half2(W[n][k0+8],W[n][k0+9]) }
//   n = nt*8 + lane/4, k0 = 16c + 2*(lane%4)
__device__ uint2 g_pb1[(size_t)2048 * 32 * 32];          // 16 MB (L1 gates: K=512)
__device__ uint2 g_pb2[(size_t)2048 * 64 * 32];          // 32 MB (L2 gates: K=1024)
// proj weights packed in B-fragment order (fp16): pr[nt(64)][c(256)][lane(32)]
__device__ uint2 g_pr1[(size_t)64 * 256 * 32];           // 4 MB
__device__ uint2 g_pr2[(size_t)64 * 256 * 32];           // 4 MB
__device__ float g_out1[(size_t)(T_STEPS + 1) * BATCH * PROJ];
__device__ float g_out2[(size_t)(T_STEPS + 1) * BATCH * PROJ];
__device__ float g_c1[BATCH * HID];
__device__ float g_c2[BATCH * HID];
__device__ float g_g1h[BATCH * HID];
__device__ float g_g2h[BATCH * HID];
__device__ int   g_counts[T_STEPS];
__device__ int   g_offsets[T_STEPS + 1];

__device__ volatile unsigned g_genv;   // monotonic across replays
__device__ unsigned g_arrive;          // self-resetting

// ---------------------------------------------------------------------------
// helpers
// ---------------------------------------------------------------------------
__device__ __forceinline__ float sigf(float x) { return 1.f / (1.f + expf(-x)); }

__device__ __forceinline__ uint32_t h2u(float2 f) {
    __half2 h = __float22half2_rn(f);
    return *(uint32_t*)&h;
}
__device__ __forceinline__ float2 u2f(uint32_t u) {
    return __half22float2(*(__half2*)&u);
}

// fp16 HMMA m16n8k16 (fp32 accumulate)
__device__ __forceinline__ void mma_f16(float c[4], const uint32_t a[4],
                                        const uint32_t b[2]) {
    asm volatile(
        "mma.sync.aligned.m16n8k16.row.col.f32.f16.f16.f32 "
        "{%0,%1,%2,%3}, {%4,%5,%6,%7}, {%8,%9}, {%0,%1,%2,%3};\n"
        : "+f"(c[0]), "+f"(c[1]), "+f"(c[2]), "+f"(c[3])
        : "r"(a[0]), "r"(a[1]), "r"(a[2]), "r"(a[3]), "r"(b[0]), "r"(b[1]));
}

// ---------------------------------------------------------------------------
// grid-wide barrier
// ---------------------------------------------------------------------------
__device__ __forceinline__ void gsync(unsigned& gen) {
    __syncthreads();
    if (threadIdx.x == 0) {
        unsigned next = gen + 1;
        __threadfence();
        if (atomicAdd(&g_arrive, 1u) == (unsigned)(NBLK - 1)) {
            g_arrive = 0u;
            __threadfence();
            g_genv = next;
        } else {
            while (g_genv != next) {}
            __threadfence();
        }
        gen = next;
    }
    __syncthreads();
}

// ---------------------------------------------------------------------------
// Fused prep: pack gate+proj weights into HMMA fragment order (fp16),
// zero states, packed-seq counts.
// blocks: [0,2048) pb1 | [2048,4096) pb2 | [4096,6144) pr1 | [6144,8192) pr2
//         8192 counts | (8192,10241) zero
// ---------------------------------------------------------------------------
__global__ void prep_kernel(const float* __restrict__ W_hh1,
                            const float* __restrict__ W_ih2,
                            const float* __restrict__ W_hh2,
                            const float* __restrict__ W_hr1,
                            const float* __restrict__ W_hr2,
                            const int* __restrict__ lens) {
    int bid = blockIdx.x;
    int tid = threadIdx.x;
    if (bid < 2048) {                       // pb1: nt = bid, 32 chunks
        int nt = bid;
        #pragma unroll
        for (int j = 0; j < 4; j++) {
            int i = tid + j * 256;          // 0..1023
            int c = i >> 5, lane = i & 31;
            int gr = lane >> 2, tc = lane & 3;
            int n = nt * 8 + gr;
            int k0 = 16 * c + 2 * tc;
            const float* src = W_hh1 + (size_t)n * 512;
            float2 f0 = *(const float2*)(src + k0);
            float2 f1 = *(const float2*)(src + k0 + 8);
            g_pb1[(size_t)(nt * 32 + c) * 32 + lane] = make_uint2(h2u(f0), h2u(f1));
        }
    } else if (bid < 4096) {                // pb2: nt = bid-2048, 64 chunks
        int nt = bid - 2048;
        #pragma unroll
        for (int j = 0; j < 8; j++) {
            int i = tid + j * 256;          // 0..2047
            int c = i >> 5, lane = i & 31;
            int gr = lane >> 2, tc = lane & 3;
            int n = nt * 8 + gr;
            int k0 = 16 * c + 2 * tc;
            const float* src = (c < 32) ? (W_ih2 + (size_t)n * 1280 + k0)
                                        : (W_hh2 + (size_t)n * 512 + (k0 - 512));
            float2 f0 = *(const float2*)src;
            float2 f1 = *(const float2*)(src + 8);
            g_pb2[(size_t)(nt * 64 + c) * 32 + lane] = make_uint2(h2u(f0), h2u(f1));
        }
    } else if (bid < 8192) {                // proj fragment pack (1 entry/thread)
        int layer = (bid >= 6144);
        const float* W = layer ? W_hr2 : W_hr1;
        uint2* dst = layer ? g_pr2 : g_pr1;
        int e = (bid - (layer ? 6144 : 4096)) * 256 + tid;
        int lane = e & 31;
        int c = (e >> 5) & 255;
        int nt = e >> 13;
        int n = nt * 8 + (lane >> 2);
        int k0 = 16 * c + 2 * (lane & 3);
        float2 f0 = *(const float2*)(W + (size_t)n * HID + k0);
        float2 f1 = *(const float2*)(W + (size_t)n * HID + k0 + 8);
        dst[e] = make_uint2(h2u(f0), h2u(f1));
    } else if (bid == 8192) {               // counts
        int t = tid;
        int c = 0;
        #pragma unroll
        for (int b = 0; b < BATCH; b++) c += (lens[b] > t) ? 1 : 0;
        g_counts[t] = c;
        __syncthreads();
        if (t == 0) {
            int s = 0;
            for (int i = 0; i < T_STEPS; i++) { g_offsets[i] = s; s += g_counts[i]; }
            g_offsets[T_STEPS] = s;
        }
    } else {                                // zero
        const size_t n1 = (size_t)(T_STEPS + 1) * BATCH * PROJ;
        const size_t nc = (size_t)BATCH * HID;
        const size_t tot = 2 * n1 + 2 * nc;
        size_t base = (size_t)(bid - 8193) * 256 + tid;
        for (size_t i = base; i < tot; i += (size_t)2048 * 256) {
            if (i < n1)               g_out1[i] = 0.f;
            else if (i < 2 * n1)      g_out2[i - n1] = 0.f;
            else if (i < 2 * n1 + nc) g_c1[i - 2 * n1] = 0.f;
            else                      g_c2[i - 2 * n1 - nc] = 0.f;
        }
    }
}

// ---------------------------------------------------------------------------
// Phase A GEMM on tensor cores: 3xFP16 split HMMA (fp32-grade accuracy).
// ---------------------------------------------------------------------------
__global__ void __launch_bounds__(256)
sgemm_f16(const float* __restrict__ A, const float* __restrict__ B,
          const float* __restrict__ bias, float* __restrict__ C,
          int K, int lda, int ldb, int boff) {
    __shared__ uint4 afh[256], afl[256];     // M side: 8 mt x 32 lanes
    __shared__ uint2 bfh[512], bfl[512];     // N side: 16 nt x 32 lanes

    const int tid = threadIdx.x;
    const int m0 = blockIdx.y * 128, n0 = blockIdx.x * 128;
    const int warp = tid >> 5, lane = tid & 31;
    const int mtb = (warp >> 2) * 4;
    const int ntb = (warp & 3) * 4;
    const int g  = lane >> 2;
    const int tk = lane & 3;

    float c[4][4][4];
    #pragma unroll
    for (int mt = 0; mt < 4; mt++)
        #pragma unroll
        for (int nt = 0; nt < 4; nt++)
            #pragma unroll
            for (int i = 0; i < 4; i++) c[mt][nt][i] = 0.f;

    for (int k0 = 0; k0 < K; k0 += 16) {
        __syncthreads();
        {
            int mt = tid >> 5, ln = tid & 31;
            int gr = ln >> 2, tc = ln & 3;
            int r0 = m0 + mt * 16 + gr;
            int ca = k0 + 2 * tc, cb = ca + 8;
            float2 fa0 = (ca < K) ? *(const float2*)(A + (size_t)r0 * lda + ca)
                                  : make_float2(0.f, 0.f);
            float2 fa1 = (ca < K) ? *(const float2*)(A + (size_t)(r0 + 8) * lda + ca)
                                  : make_float2(0.f, 0.f);
            float2 fa2 = (cb < K) ? *(const float2*)(A + (size_t)r0 * lda + cb)
                                  : make_float2(0.f, 0.f);
            float2 fa3 = (cb < K) ? *(const float2*)(A + (size_t)(r0 + 8) * lda + cb)
                                  : make_float2(0.f, 0.f);
            uint32_t h0 = h2u(fa0), h1 = h2u(fa1), h2 = h2u(fa2), h3 = h2u(fa3);
            float2 d0 = u2f(h0), d1 = u2f(h1), d2 = u2f(h2), d3 = u2f(h3);
            uint32_t l0 = h2u(make_float2(fa0.x - d0.x, fa0.y - d0.y));
            uint32_t l1 = h2u(make_float2(fa1.x - d1.x, fa1.y - d1.y));
            uint32_t l2 = h2u(make_float2(fa2.x - d2.x, fa2.y - d2.y));
            uint32_t l3 = h2u(make_float2(fa3.x - d3.x, fa3.y - d3.y));
            afh[tid] = make_uint4(h0, h1, h2, h3);
            afl[tid] = make_uint4(l0, l1, l2, l3);
        }
        #pragma unroll
        for (int e = 0; e < 2; e++) {
            int i = tid + e * 256;
            int nt = i >> 5, ln = i & 31;
            int gr = ln >> 2, tc = ln & 3;
            int n = n0 + nt * 8 + gr;
            int ca = k0 + 2 * tc, cb = ca + 8;
            float2 f0 = (ca < K) ? *(const float2*)(B + (size_t)n * ldb + boff + ca)
                                 : make_float2(0.f, 0.f);
            float2 f1 = (cb < K) ? *(const float2*)(B + (size_t)n * ldb + boff + cb)
                                 : make_float2(0.f, 0.f);
            uint32_t h0 = h2u(f0), h1 = h2u(f1);
            float2 d0 = u2f(h0), d1 = u2f(h1);
            uint32_t l0 = h2u(make_float2(f0.x - d0.x, f0.y - d0.y));
            uint32_t l1 = h2u(make_float2(f1.x - d1.x, f1.y - d1.y));
            bfh[i] = make_uint2(h0, h1);
            bfl[i] = make_uint2(l0, l1);
        }
        __syncthreads();

        uint32_t ah[4][4], al[4][4], bh[4][2], bl[4][2];
        #pragma unroll
        for (int mt = 0; mt < 4; mt++) {
            uint4 vh = afh[(mtb + mt) * 32 + lane];
            uint4 vl = afl[(mtb + mt) * 32 + lane];
            ah[mt][0] = vh.x; ah[mt][1] = vh.y; ah[mt][2] = vh.z; ah[mt][3] = vh.w;
            al[mt][0] = vl.x; al[mt][1] = vl.y; al[mt][2] = vl.z; al[mt][3] = vl.w;
        }
        #pragma unroll
        for (int nt = 0; nt < 4; nt++) {
            uint2 vh = bfh[(ntb + nt) * 32 + lane];
            uint2 vl = bfl[(ntb + nt) * 32 + lane];
            bh[nt][0] = vh.x; bh[nt][1] = vh.y;
            bl[nt][0] = vl.x; bl[nt][1] = vl.y;
        }
        #pragma unroll
        for (int mt = 0; mt < 4; mt++)
            #pragma unroll
            for (int nt = 0; nt < 4; nt++) {
                mma_f16(c[mt][nt], ah[mt], bh[nt]);   // hi*hi
                mma_f16(c[mt][nt], ah[mt], bl[nt]);   // hi*lo
                mma_f16(c[mt][nt], al[mt], bh[nt]);   // lo*hi
            }
    }

    #pragma unroll
    for (int nt = 0; nt < 4; nt++) {
        int col = n0 + (ntb + nt) * 8 + 2 * tk;
        float b0 = bias[col], b1 = bias[col + 1];
        #pragma unroll
        for (int mt = 0; mt < 4; mt++) {
            int row0 = m0 + (mtb + mt) * 16 + g;
            float2 v0 = {c[mt][nt][0] + b0, c[mt][nt][1] + b1};
            float2 v1 = {c[mt][nt][2] + b0, c[mt][nt][3] + b1};
            __stcs((float2*)(C + (size_t)row0 * G4H + col), v0);
            __stcs((float2*)(C + (size_t)(row0 + 8) * G4H + col), v1);
        }
    }
}

// ---------------------------------------------------------------------------
// Stage h into A-fragment layout (fp16): af[(c*32+lane)*4 + r] uint32.
// ---------------------------------------------------------------------------
template <int NC>
__device__ __forceinline__ void stage_af(const float* __restrict__ src1,
                                         const float* __restrict__ src2,
                                         uint32_t* af) {
    const int tid = threadIdx.x;
    for (int i = tid; i < NC * 32; i += 512) {
        int c = i >> 5, lane = i & 31;
        int gr = lane >> 2, tc = lane & 3;
        int k0 = 16 * c + 2 * tc;
        const float* s = (NC == 32 || k0 < 512) ? (src1 + k0) : (src2 + k0 - 512);
        float2 f0 = *(const float2*)(s + gr * PROJ);
        float2 f1 = *(const float2*)(s + (gr + 8) * PROJ);
        float2 f2 = *(const float2*)(s + gr * PROJ + 8);
        float2 f3 = *(const float2*)(s + (gr + 8) * PROJ + 8);
        *(uint4*)(af + (size_t)i * 4) =
            make_uint4(h2u(f0), h2u(f1), h2u(f2), h2u(f3));
    }
}

// ---------------------------------------------------------------------------
// Gate phase via HMMA: xg prefetch hoisted; dual acc chains on the 64-k loop.
// ---------------------------------------------------------------------------
template <bool DO1, bool DO2>
__device__ __forceinline__ void gate_mma(
    const uint32_t* af, float* zbuf1, float* zbuf2,
    const float* __restrict__ xg1p, const float* __restrict__ xg2p)
{
    const int w = threadIdx.x >> 5, lane = threadIdx.x & 31;
    const int gate = w >> 2, jj8 = (w & 3) << 3;
    const int gr = lane >> 2, tc = lane & 3;
    const int ntg = gate * 512 + blockIdx.x * 4 + (w & 3);

    const int jl = jj8 + 2 * tc;
    const int rowg = gate * HID + blockIdx.x * 32 + jl;

    // prefetch xg (DRAM stream) so its latency overlaps the MMA weight loads
    float2 x1a, x1b, x2a, x2b;
    if (DO1) {
        x1a = __ldcs((const float2*)(xg1p + (size_t)gr * G4H + rowg));
        x1b = __ldcs((const float2*)(xg1p + (size_t)(gr + 8) * G4H + rowg));
    }
    if (DO2) {
        x2a = __ldcs((const float2*)(xg2p + (size_t)gr * G4H + rowg));
        x2b = __ldcs((const float2*)(xg2p + (size_t)(gr + 8) * G4H + rowg));
    }

    float acc1[4] = {0.f, 0.f, 0.f, 0.f};
    float acc2[4] = {0.f, 0.f, 0.f, 0.f};
    float acc2b[4] = {0.f, 0.f, 0.f, 0.f};

    if (DO2) {
        const uint2* bp = g_pb2 + (size_t)ntg * 64 * 32 + lane;
        #pragma unroll 8
        for (int c = 0; c < 32; c++) {
            uint4 a0 = *(const uint4*)(af + (size_t)((2 * c) * 32 + lane) * 4);
            uint4 a1 = *(const uint4*)(af + (size_t)((2 * c + 1) * 32 + lane) * 4);
            uint2 b0 = bp[(size_t)(2 * c) * 32];
            uint2 b1 = bp[(size_t)(2 * c + 1) * 32];
            uint32_t af0[4] = {a0.x, a0.y, a0.z, a0.w};
            uint32_t af1[4] = {a1.x, a1.y, a1.z, a1.w};
            uint32_t bf0[2] = {b0.x, b0.y};
            uint32_t bf1[2] = {b1.x, b1.y};
            mma_f16(acc2, af0, bf0);     // even chunks -> chain A
            mma_f16(acc2b, af1, bf1);    // odd chunks  -> chain B
        }
    }
    if (DO1) {
        const uint2* bp = g_pb1 + (size_t)ntg * 32 * 32 + lane;
        #pragma unroll 8
        for (int c = 0; c < 32; c++) {
            uint4 av = *(const uint4*)(af + (size_t)(c * 32 + lane) * 4);
            uint2 bv = bp[(size_t)c * 32];
            uint32_t a[4] = {av.x, av.y, av.z, av.w};
            uint32_t b[2] = {bv.x, bv.y};
            mma_f16(acc1, a, b);
        }
    }

    if (DO1) {
        float2 z0 = {acc1[0] + x1a.x, acc1[1] + x1a.y};
        float2 z1 = {acc1[2] + x1b.x, acc1[3] + x1b.y};
        *(float2*)&zbuf1[gate * 512 + gr * 32 + jl] = z0;
        *(float2*)&zbuf1[gate * 512 + (gr + 8) * 32 + jl] = z1;
    }
    if (DO2) {
        float2 z0 = {acc2[0] + acc2b[0] + x2a.x, acc2[1] + acc2b[1] + x2a.y};
        float2 z1 = {acc2[2] + acc2b[2] + x2b.x, acc2[3] + acc2b[3] + x2b.y};
        *(float2*)&zbuf2[gate * 512 + gr * 32 + jl] = z0;
        *(float2*)&zbuf2[gate * 512 + (gr + 8) * 32 + jl] = z1;
    }
}

// ---------------------------------------------------------------------------
// Cell update for both layers (c-state in registers).
// ---------------------------------------------------------------------------
template <bool DO1, bool DO2>
__device__ __forceinline__ void cell_update(
    const float* zbuf1, const float* zbuf2,
    float& c1r, float& c2r, bool last1, bool last2)
{
    const int tid = threadIdx.x;
    const int b = tid >> 5, jl = tid & 31;
    const size_t off = (size_t)b * HID + blockIdx.x * 32 + jl;
    if (DO1) {
        float zi = zbuf1[0 * 512 + b * 32 + jl];
        float zf = zbuf1[1 * 512 + b * 32 + jl];
        float zg = zbuf1[2 * 512 + b * 32 + jl];
        float zo = zbuf1[3 * 512 + b * 32 + jl];
        float cn = sigf(zf) * c1r + sigf(zi) * tanhf(zg);
        c1r = cn;
        g_g1h[off] = sigf(zo) * tanhf(cn);
        if (last1) g_c1[off] = cn;
    }
    if (DO2) {
        float zi = zbuf2[0 * 512 + b * 32 + jl];
        float zf = zbuf2[1 * 512 + b * 32 + jl];
        float zg = zbuf2[2 * 512 + b * 32 + jl];
        float zo = zbuf2[3 * 512 + b * 32 + jl];
        float cn = sigf(zf) * c2r + sigf(zi) * tanhf(zg);
        c2r = cn;
        g_g2h[off] = sigf(zo) * tanhf(cn);
        if (last2) g_c2[off] = cn;
    }
}

// ---------------------------------------------------------------------------
// Proj phase via HMMA: stage gh slice as A-fragments (both layers in one
// pass over 512 threads), then 8 MMAs per warp per layer + direct atomics.
// Block (pt, kc): p-tile = 128 (16 n-tiles; warp w -> nt = pt*16+w),
// k-chunk = 128 (8 mma chunks).
// ---------------------------------------------------------------------------
template <bool DO1, bool DO2>
__device__ __forceinline__ void stage_paf(int kb, uint32_t* paf1, uint32_t* paf2) {
    const int tid = threadIdx.x;
    const int layer = tid >> 8;
    if ((layer == 0 && !DO1) || (layer == 1 && !DO2)) return;
    const int i = tid & 255;
    const int cl = i >> 5, lane = i & 31;
    const int gr = lane >> 2, tc = lane & 3;
    const int k0 = kb + 16 * cl + 2 * tc;
    const float* gh = layer ? g_g2h : g_g1h;
    uint32_t* paf = layer ? paf2 : paf1;
    float2 f0 = __ldcs((const float2*)(gh + (size_t)gr * HID + k0));
    float2 f1 = __ldcs((const float2*)(gh + (size_t)(gr + 8) * HID + k0));
    float2 f2 = __ldcs((const float2*)(gh + (size_t)gr * HID + k0 + 8));
    float2 f3 = __ldcs((const float2*)(gh + (size_t)(gr + 8) * HID + k0 + 8));
    *(uint4*)(paf + (size_t)i * 4) = make_uint4(h2u(f0), h2u(f1), h2u(f2), h2u(f3));
}

template <bool DO1, bool DO2>
__device__ __forceinline__ void proj_mma(
    const uint32_t* paf1, const uint32_t* paf2,
    float* __restrict__ hout1, float* __restrict__ hout2, int pt, int kc)
{
    const int w = threadIdx.x >> 5, lane = threadIdx.x & 31;
    const int gr = lane >> 2, tc = lane & 3;
    const int ntg = pt * 16 + w;
    const int pg = ntg * 8 + 2 * tc;

    if (DO1) {
        float acc[4] = {0.f, 0.f, 0.f, 0.f};
        const uint2* bp = g_pr1 + ((size_t)ntg * 256 + kc * 8) * 32 + lane;
        #pragma unroll
        for (int cl = 0; cl < 8; cl++) {
            uint4 av = *(const uint4*)(paf1 + (size_t)(cl * 32 + lane) * 4);
            uint2 bv = bp[(size_t)cl * 32];
            uint32_t a[4] = {av.x, av.y, av.z, av.w};
            uint32_t b[2] = {bv.x, bv.y};
            mma_f16(acc, a, b);
        }
        atomicAdd(hout1 + (size_t)gr * PROJ + pg,           acc[0]);
        atomicAdd(hout1 + (size_t)gr * PROJ + pg + 1,       acc[1]);
        atomicAdd(hout1 + (size_t)(gr + 8) * PROJ + pg,     acc[2]);
        atomicAdd(hout1 + (size_t)(gr + 8) * PROJ + pg + 1, acc[3]);
    }
    if (DO2) {
        float acc[4] = {0.f, 0.f, 0.f, 0.f};
        const uint2* bp = g_pr2 + ((size_t)ntg * 256 + kc * 8) * 32 + lane;
        #pragma unroll
        for (int cl = 0; cl < 8; cl++) {
            uint4 av = *(const uint4*)(paf2 + (size_t)(cl * 32 + lane) * 4);
            uint2 bv = bp[(size_t)cl * 32];
            uint32_t a[4] = {av.x, av.y, av.z, av.w};
            uint32_t b[2] = {bv.x, bv.y};
            mma_f16(acc, a, b);
        }
        atomicAdd(hout2 + (size_t)gr * PROJ + pg,           acc[0]);
        atomicAdd(hout2 + (size_t)gr * PROJ + pg + 1,       acc[1]);
        atomicAdd(hout2 + (size_t)(gr + 8) * PROJ + pg,     acc[2]);
        atomicAdd(hout2 + (size_t)(gr + 8) * PROJ + pg + 1, acc[3]);
    }
}

// ---------------------------------------------------------------------------
// Persistent recurrence: HMMA gates + HMMA proj, fused dual-layer phases.
// ---------------------------------------------------------------------------
__global__ void __launch_bounds__(512, 1) recurrence_kernel() {
    extern __shared__ float smem[];
    uint32_t* af = (uint32_t*)smem;                  // [0, 8192) uint32
    float* zbuf1 = smem + 8192;
    float* zbuf2 = smem + 10240;
    uint32_t* paf1 = (uint32_t*)smem;                // proj aliases
    uint32_t* paf2 = (uint32_t*)smem + 1024;

    const int pt = blockIdx.x & 3;
    const int kc = blockIdx.x >> 2;
    const int kb = kc * 128;

    unsigned gen = g_genv;
    float c1r = 0.f, c2r = 0.f;

    // ---- prologue: G1(0) ----
    stage_af<32>(g_out1, nullptr, af);
    __syncthreads();
    gate_mma<true, false>(af, zbuf1, zbuf2, g_xg1, nullptr);
    __syncthreads();
    cell_update<true, false>(zbuf1, zbuf2, c1r, c2r, false, false);
    gsync(gen);
    // ---- P1(0) -> out1[1] ----
    stage_paf<true, false>(kb, paf1, paf2);
    __syncthreads();
    proj_mma<true, false>(paf1, paf2,
                          g_out1 + (size_t)1 * (BATCH * PROJ), nullptr, pt, kc);
    gsync(gen);

    for (int t = 0; t < T_STEPS - 1; t++) {
        // fused gate phase: G1(t+1) + G2(t)
        stage_af<64>(g_out1 + (size_t)(t + 1) * (BATCH * PROJ),
                     g_out2 + (size_t)t * (BATCH * PROJ), af);
        __syncthreads();
        gate_mma<true, true>(af, zbuf1, zbuf2,
                             g_xg1 + (size_t)(t + 1) * BATCH * G4H,
                             g_xg2 + (size_t)t * BATCH * G4H);
        __syncthreads();
        cell_update<true, true>(zbuf1, zbuf2, c1r, c2r,
                                (t + 1 == T_STEPS - 1), false);
        gsync(gen);
        // fused proj phase: P1(t+1) + P2(t)
        stage_paf<true, true>(kb, paf1, paf2);
        __syncthreads();
        proj_mma<true, true>(paf1, paf2,
                             g_out1 + (size_t)(t + 2) * (BATCH * PROJ),
                             g_out2 + (size_t)(t + 1) * (BATCH * PROJ), pt, kc);
        gsync(gen);
    }

    // ---- tail: G2(255) | P2(255) ----
    {
        int t = T_STEPS - 1;
        stage_af<64>(g_out1 + (size_t)(t + 1) * (BATCH * PROJ),
                     g_out2 + (size_t)t * (BATCH * PROJ), af);
        __syncthreads();
        gate_mma<false, true>(af, zbuf1, zbuf2, nullptr,
                              g_xg2 + (size_t)t * BATCH * G4H);
        __syncthreads();
        cell_update<false, true>(zbuf1, zbuf2, c1r, c2r, false, true);
        gsync(gen);
        stage_paf<false, true>(kb, paf1, paf2);
        __syncthreads();
        proj_mma<false, true>(paf1, paf2, nullptr,
                              g_out2 + (size_t)(t + 1) * (BATCH * PROJ), pt, kc);
    }
}

// ---------------------------------------------------------------------------
// Heads: one warp per packed token
// ---------------------------------------------------------------------------
__global__ void __launch_bounds__(512) heads_kernel(
    const float* __restrict__ Wp, const float* __restrict__ bp,
    const float* __restrict__ Wa, const float* __restrict__ ba,
    float* __restrict__ out, int total) {
    const int t = blockIdx.x;
    const int w = threadIdx.x >> 5;
    const int lane = threadIdx.x & 31;
    if (w >= g_counts[t]) return;
    const int b = w;
    const int tok = g_offsets[t] + b;

    const float* o1 = g_out1 + (size_t)(t + 1) * (BATCH * PROJ) + (size_t)b * PROJ;
    const float* o2 = g_out2 + (size_t)(t + 1) * (BATCH * PROJ) + (size_t)b * PROJ;
    float v[16];
    #pragma unroll
    for (int i = 0; i < 16; i++) v[i] = o1[lane + 32 * i] + o2[lane + 32 * i];

    __shared__ float sp[16][20];
    __shared__ float sa[16][20];
    #pragma unroll
    for (int o = 0; o < 20; o++) {
        float s1 = 0.f, s2 = 0.f;
        #pragma unroll
        for (int i = 0; i < 16; i++) {
            float x = v[i];
            s1 = fmaf(x, Wp[o * PROJ + lane + 32 * i], s1);
            s2 = fmaf(x, Wa[o * PROJ + lane + 32 * i], s2);
        }
        #pragma unroll
        for (int off = 16; off; off >>= 1) {
            s1 += __shfl_xor_sync(0xffffffffu, s1, off);
            s2 += __shfl_xor_sync(0xffffffffu, s2, off);
        }
        if (lane == 0) { sp[w][o] = s1 + bp[o]; sa[w][o] = s2 + ba[o]; }
    }
    __syncwarp();
    if (lane == 0) {
        float m = -1e30f;
        #pragma unroll
        for (int o = 0; o < 20; o++) m = fmaxf(m, sp[w][o]);
        float e[20], sum = 0.f;
        #pragma unroll
        for (int o = 0; o < 20; o++) { e[o] = expf(sp[w][o] - m); sum += e[o]; }
        float inv = 1.f / sum;
        float* aa = out + (size_t)total * 20;
        #pragma unroll
        for (int o = 0; o < 20; o++) {
            out[(size_t)tok * 20 + o] = e[o] * inv;
            aa[(size_t)tok * 20 + o]  = sa[w][o];
        }
    }
}

// ---------------------------------------------------------------------------
// Final states: h1, c1, h2, c2
// ---------------------------------------------------------------------------
__global__ void finalize_kernel(float* __restrict__ out, int total) {
    const size_t base = (size_t)total * 40;
    const int nH = BATCH * PROJ;
    const int nC = BATCH * HID;
    int idx = blockIdx.x * blockDim.x + threadIdx.x;
    if (idx >= 2 * (nH + nC)) return;
    float v;
    if (idx < nH)                v = g_out1[(size_t)T_STEPS * nH + idx];
    else if (idx < nH + nC)      v = g_c1[idx - nH];
    else if (idx < 2 * nH + nC)  v = g_out2[(size_t)T_STEPS * nH + (idx - nH - nC)];
    else                         v = g_c2[idx - 2 * nH - nC];
    out[base + idx] = v;
}

// ---------------------------------------------------------------------------
// Host launch
// ---------------------------------------------------------------------------
extern "C" void kernel_launch(void* const* d_in, const int* in_sizes, int n_in,
                              void* d_out, int out_size) {
    const float* uncon  = (const float*)d_in[0];
    const float* con    = (const float*)d_in[1];
    const int*   lens   = (const int*)d_in[2];
    const float* W_ih1  = (const float*)d_in[3];
    const float* b1     = (const float*)d_in[4];
    const float* W_hh1  = (const float*)d_in[5];
    const float* W_hr1  = (const float*)d_in[6];
    const float* W_ih2  = (const float*)d_in[7];
    const float* b2     = (const float*)d_in[8];
    const float* W_hh2  = (const float*)d_in[9];
    const float* W_hr2  = (const float*)d_in[10];
    const float* W_pssm = (const float*)d_in[11];
    const float* b_pssm = (const float*)d_in[12];
    const float* W_aa   = (const float*)d_in[13];
    const float* b_aa   = (const float*)d_in[14];
    float* out = (float*)d_out;

    const int total = (out_size - 2 * (BATCH * PROJ + BATCH * HID)) / 40;

    float *p_xg1, *p_xg2;
    cudaGetSymbolAddress((void**)&p_xg1, g_xg1);
    cudaGetSymbolAddress((void**)&p_xg2, g_xg2);

    cudaFuncSetAttribute(recurrence_kernel,
                         cudaFuncAttributeMaxDynamicSharedMemorySize, SM_TOTAL_B);

    // 1: fused prep (HMMA fragment packs + zero + counts)
    prep_kernel<<<10241, 256>>>(W_hh1, W_ih2, W_hh2, W_hr1, W_hr2, lens);
    // 2,3: Phase A on tensor cores (3xFP16 split HMMA)
    sgemm_f16<<<dim3(G4H / 128, (T_STEPS * BATCH) / 128), 256>>>(
        uncon, W_ih1, b1, p_xg1, F1, F1, F1, 0);
    sgemm_f16<<<dim3(G4H / 128, (T_STEPS * BATCH) / 128), 256>>>(
        con, W_ih2, b2, p_xg2, F2CON, F2CON, 1280, 512);
    // 4: persistent recurrence (HMMA gates + HMMA proj)
    recurrence_kernel<<<NBLK, 512, SM_TOTAL_B>>>();
    // 5,6: heads + final states
    heads_kernel<<<T_STEPS, 512>>>(W_pssm, b_pssm, W_aa, b_aa, out, total);
    finalize_kernel<<<(2 * (BATCH * PROJ + BATCH * HID) + 255) / 256, 256>>>(out, total);
}

// round 17
// speedup vs baseline: 1.7394x; 1.0692x over previous
#include <cuda_runtime.h>
#include <cuda_fp16.h>
#include <math.h>
#include <stdint.h>

// ---------------------------------------------------------------------------
// Problem constants
// ---------------------------------------------------------------------------
#define T_STEPS 256
#define BATCH   16
#define HID     4096          // H
#define PROJ    512           // P
#define G4H     16384         // 4*H
#define F1      532
#define F2CON   768           // con_x features (1280-512)
#define NBLK    128           // persistent grid size
#define CLSZ    4             // cluster size (proj k-chunk = 4 gate j-tiles)

// persistent-kernel dynamic smem (floats):
//  gate: af (uint32) [0, 8192) | zbuf1 [8192,10240) | zbuf2 [10240,12288)
//  gh_s [12288, 13312)  (2 layers x 16 batch x 32 j — read via DSMEM by cluster)
//  proj: paf1 (uint32) [0,1024) | paf2 [1024,2048)   (aliases af)
#define SM_GH_OFF  12288
#define SM_TOTAL_F 13312
#define SM_TOTAL_B (SM_TOTAL_F * 4)     // 53248

// ---------------------------------------------------------------------------
// Device scratch (static only — no cudaMalloc allowed)
// ---------------------------------------------------------------------------
__device__ float g_xg1[(size_t)T_STEPS * BATCH * G4H];   // 268 MB
__device__ float g_xg2[(size_t)T_STEPS * BATCH * G4H];   // 268 MB
// gate weights packed in m16n8k16 B-fragment order (fp16)
__device__ uint2 g_pb1[(size_t)2048 * 32 * 32];          // 16 MB (L1 gates: K=512)
__device__ uint2 g_pb2[(size_t)2048 * 64 * 32];          // 32 MB (L2 gates: K=1024)
// proj weights packed in B-fragment order (fp16): pr[nt(64)][c(256)][lane(32)]
__device__ uint2 g_pr1[(size_t)64 * 256 * 32];           // 4 MB
__device__ uint2 g_pr2[(size_t)64 * 256 * 32];           // 4 MB
__device__ float g_out1[(size_t)(T_STEPS + 1) * BATCH * PROJ];
__device__ float g_out2[(size_t)(T_STEPS + 1) * BATCH * PROJ];
__device__ float g_c1[BATCH * HID];
__device__ float g_c2[BATCH * HID];
__device__ int   g_counts[T_STEPS];
__device__ int   g_offsets[T_STEPS + 1];

__device__ volatile unsigned g_genv;   // monotonic across replays
__device__ unsigned g_arrive;          // self-resetting

// ---------------------------------------------------------------------------
// helpers
// ---------------------------------------------------------------------------
__device__ __forceinline__ float sigf(float x) { return 1.f / (1.f + expf(-x)); }

__device__ __forceinline__ uint32_t h2u(float2 f) {
    __half2 h = __float22half2_rn(f);
    return *(uint32_t*)&h;
}
__device__ __forceinline__ float2 u2f(uint32_t u) {
    return __half22float2(*(__half2*)&u);
}

// fp16 HMMA m16n8k16 (fp32 accumulate)
__device__ __forceinline__ void mma_f16(float c[4], const uint32_t a[4],
                                        const uint32_t b[2]) {
    asm volatile(
        "mma.sync.aligned.m16n8k16.row.col.f32.f16.f16.f32 "
        "{%0,%1,%2,%3}, {%4,%5,%6,%7}, {%8,%9}, {%0,%1,%2,%3};\n"
        : "+f"(c[0]), "+f"(c[1]), "+f"(c[2]), "+f"(c[3])
        : "r"(a[0]), "r"(a[1]), "r"(a[2]), "r"(a[3]), "r"(b[0]), "r"(b[1]));
}

// cluster / DSMEM primitives
__device__ __forceinline__ void cluster_sync_() {
    asm volatile("barrier.cluster.arrive.aligned;" ::: "memory");
    asm volatile("barrier.cluster.wait.aligned;" ::: "memory");
}
__device__ __forceinline__ uint32_t s2u(const void* p) {
    uint32_t a;
    asm("{ .reg .u64 t; cvta.to.shared.u64 t, %1; cvt.u32.u64 %0, t; }"
        : "=r"(a) : "l"(p));
    return a;
}
__device__ __forceinline__ uint32_t mapa_rank(uint32_t a, int rank) {
    uint32_t r;
    asm("mapa.shared::cluster.u32 %0, %1, %2;" : "=r"(r) : "r"(a), "r"(rank));
    return r;
}
__device__ __forceinline__ float2 ld_ds2(uint32_t a) {
    float2 v;
    asm volatile("ld.shared::cluster.v2.f32 {%0,%1}, [%2];"
                 : "=f"(v.x), "=f"(v.y) : "r"(a));
    return v;
}

// ---------------------------------------------------------------------------
// grid-wide barrier
// ---------------------------------------------------------------------------
__device__ __forceinline__ void gsync(unsigned& gen) {
    __syncthreads();
    if (threadIdx.x == 0) {
        unsigned next = gen + 1;
        __threadfence();
        if (atomicAdd(&g_arrive, 1u) == (unsigned)(NBLK - 1)) {
            g_arrive = 0u;
            __threadfence();
            g_genv = next;
        } else {
            while (g_genv != next) {}
            __threadfence();
        }
        gen = next;
    }
    __syncthreads();
}

// ---------------------------------------------------------------------------
// Fused prep: pack gate+proj weights into HMMA fragment order (fp16),
// zero states, packed-seq counts.
// ---------------------------------------------------------------------------
__global__ void prep_kernel(const float* __restrict__ W_hh1,
                            const float* __restrict__ W_ih2,
                            const float* __restrict__ W_hh2,
                            const float* __restrict__ W_hr1,
                            const float* __restrict__ W_hr2,
                            const int* __restrict__ lens) {
    int bid = blockIdx.x;
    int tid = threadIdx.x;
    if (bid < 2048) {                       // pb1: nt = bid, 32 chunks
        int nt = bid;
        #pragma unroll
        for (int j = 0; j < 4; j++) {
            int i = tid + j * 256;
            int c = i >> 5, lane = i & 31;
            int gr = lane >> 2, tc = lane & 3;
            int n = nt * 8 + gr;
            int k0 = 16 * c + 2 * tc;
            const float* src = W_hh1 + (size_t)n * 512;
            float2 f0 = *(const float2*)(src + k0);
            float2 f1 = *(const float2*)(src + k0 + 8);
            g_pb1[(size_t)(nt * 32 + c) * 32 + lane] = make_uint2(h2u(f0), h2u(f1));
        }
    } else if (bid < 4096) {                // pb2: nt = bid-2048, 64 chunks
        int nt = bid - 2048;
        #pragma unroll
        for (int j = 0; j < 8; j++) {
            int i = tid + j * 256;
            int c = i >> 5, lane = i & 31;
            int gr = lane >> 2, tc = lane & 3;
            int n = nt * 8 + gr;
            int k0 = 16 * c + 2 * tc;
            const float* src = (c < 32) ? (W_ih2 + (size_t)n * 1280 + k0)
                                        : (W_hh2 + (size_t)n * 512 + (k0 - 512));
            float2 f0 = *(const float2*)src;
            float2 f1 = *(const float2*)(src + 8);
            g_pb2[(size_t)(nt * 64 + c) * 32 + lane] = make_uint2(h2u(f0), h2u(f1));
        }
    } else if (bid < 8192) {                // proj fragment pack
        int layer = (bid >= 6144);
        const float* W = layer ? W_hr2 : W_hr1;
        uint2* dst = layer ? g_pr2 : g_pr1;
        int e = (bid - (layer ? 6144 : 4096)) * 256 + tid;
        int lane = e & 31;
        int c = (e >> 5) & 255;
        int nt = e >> 13;
        int n = nt * 8 + (lane >> 2);
        int k0 = 16 * c + 2 * (lane & 3);
        float2 f0 = *(const float2*)(W + (size_t)n * HID + k0);
        float2 f1 = *(const float2*)(W + (size_t)n * HID + k0 + 8);
        dst[e] = make_uint2(h2u(f0), h2u(f1));
    } else if (bid == 8192) {               // counts
        int t = tid;
        int c = 0;
        #pragma unroll
        for (int b = 0; b < BATCH; b++) c += (lens[b] > t) ? 1 : 0;
        g_counts[t] = c;
        __syncthreads();
        if (t == 0) {
            int s = 0;
            for (int i = 0; i < T_STEPS; i++) { g_offsets[i] = s; s += g_counts[i]; }
            g_offsets[T_STEPS] = s;
        }
    } else {                                // zero
        const size_t n1 = (size_t)(T_STEPS + 1) * BATCH * PROJ;
        const size_t nc = (size_t)BATCH * HID;
        const size_t tot = 2 * n1 + 2 * nc;
        size_t base = (size_t)(bid - 8193) * 256 + tid;
        for (size_t i = base; i < tot; i += (size_t)2048 * 256) {
            if (i < n1)               g_out1[i] = 0.f;
            else if (i < 2 * n1)      g_out2[i - n1] = 0.f;
            else if (i < 2 * n1 + nc) g_c1[i - 2 * n1] = 0.f;
            else                      g_c2[i - 2 * n1 - nc] = 0.f;
        }
    }
}

// ---------------------------------------------------------------------------
// Phase A GEMM on tensor cores: 3xFP16 split HMMA (fp32-grade accuracy).
// ---------------------------------------------------------------------------
__global__ void __launch_bounds__(256)
sgemm_f16(const float* __restrict__ A, const float* __restrict__ B,
          const float* __restrict__ bias, float* __restrict__ C,
          int K, int lda, int ldb, int boff) {
    __shared__ uint4 afh[256], afl[256];
    __shared__ uint2 bfh[512], bfl[512];

    const int tid = threadIdx.x;
    const int m0 = blockIdx.y * 128, n0 = blockIdx.x * 128;
    const int warp = tid >> 5, lane = tid & 31;
    const int mtb = (warp >> 2) * 4;
    const int ntb = (warp & 3) * 4;
    const int g  = lane >> 2;
    const int tk = lane & 3;

    float c[4][4][4];
    #pragma unroll
    for (int mt = 0; mt < 4; mt++)
        #pragma unroll
        for (int nt = 0; nt < 4; nt++)
            #pragma unroll
            for (int i = 0; i < 4; i++) c[mt][nt][i] = 0.f;

    for (int k0 = 0; k0 < K; k0 += 16) {
        __syncthreads();
        {
            int mt = tid >> 5, ln = tid & 31;
            int gr = ln >> 2, tc = ln & 3;
            int r0 = m0 + mt * 16 + gr;
            int ca = k0 + 2 * tc, cb = ca + 8;
            float2 fa0 = (ca < K) ? *(const float2*)(A + (size_t)r0 * lda + ca)
                                  : make_float2(0.f, 0.f);
            float2 fa1 = (ca < K) ? *(const float2*)(A + (size_t)(r0 + 8) * lda + ca)
                                  : make_float2(0.f, 0.f);
            float2 fa2 = (cb < K) ? *(const float2*)(A + (size_t)r0 * lda + cb)
                                  : make_float2(0.f, 0.f);
            float2 fa3 = (cb < K) ? *(const float2*)(A + (size_t)(r0 + 8) * lda + cb)
                                  : make_float2(0.f, 0.f);
            uint32_t h0 = h2u(fa0), h1 = h2u(fa1), h2 = h2u(fa2), h3 = h2u(fa3);
            float2 d0 = u2f(h0), d1 = u2f(h1), d2 = u2f(h2), d3 = u2f(h3);
            uint32_t l0 = h2u(make_float2(fa0.x - d0.x, fa0.y - d0.y));
            uint32_t l1 = h2u(make_float2(fa1.x - d1.x, fa1.y - d1.y));
            uint32_t l2 = h2u(make_float2(fa2.x - d2.x, fa2.y - d2.y));
            uint32_t l3 = h2u(make_float2(fa3.x - d3.x, fa3.y - d3.y));
            afh[tid] = make_uint4(h0, h1, h2, h3);
            afl[tid] = make_uint4(l0, l1, l2, l3);
        }
        #pragma unroll
        for (int e = 0; e < 2; e++) {
            int i = tid + e * 256;
            int nt = i >> 5, ln = i & 31;
            int gr = ln >> 2, tc = ln & 3;
            int n = n0 + nt * 8 + gr;
            int ca = k0 + 2 * tc, cb = ca + 8;
            float2 f0 = (ca < K) ? *(const float2*)(B + (size_t)n * ldb + boff + ca)
                                 : make_float2(0.f, 0.f);
            float2 f1 = (cb < K) ? *(const float2*)(B + (size_t)n * ldb + boff + cb)
                                 : make_float2(0.f, 0.f);
            uint32_t h0 = h2u(f0), h1 = h2u(f1);
            float2 d0 = u2f(h0), d1 = u2f(h1);
            uint32_t l0 = h2u(make_float2(f0.x - d0.x, f0.y - d0.y));
            uint32_t l1 = h2u(make_float2(f1.x - d1.x, f1.y - d1.y));
            bfh[i] = make_uint2(h0, h1);
            bfl[i] = make_uint2(l0, l1);
        }
        __syncthreads();

        uint32_t ah[4][4], al[4][4], bh[4][2], bl[4][2];
        #pragma unroll
        for (int mt = 0; mt < 4; mt++) {
            uint4 vh = afh[(mtb + mt) * 32 + lane];
            uint4 vl = afl[(mtb + mt) * 32 + lane];
            ah[mt][0] = vh.x; ah[mt][1] = vh.y; ah[mt][2] = vh.z; ah[mt][3] = vh.w;
            al[mt][0] = vl.x; al[mt][1] = vl.y; al[mt][2] = vl.z; al[mt][3] = vl.w;
        }
        #pragma unroll
        for (int nt = 0; nt < 4; nt++) {
            uint2 vh = bfh[(ntb + nt) * 32 + lane];
            uint2 vl = bfl[(ntb + nt) * 32 + lane];
            bh[nt][0] = vh.x; bh[nt][1] = vh.y;
            bl[nt][0] = vl.x; bl[nt][1] = vl.y;
        }
        #pragma unroll
        for (int mt = 0; mt < 4; mt++)
            #pragma unroll
            for (int nt = 0; nt < 4; nt++) {
                mma_f16(c[mt][nt], ah[mt], bh[nt]);   // hi*hi
                mma_f16(c[mt][nt], ah[mt], bl[nt]);   // hi*lo
                mma_f16(c[mt][nt], al[mt], bh[nt]);   // lo*hi
            }
    }

    #pragma unroll
    for (int nt = 0; nt < 4; nt++) {
        int col = n0 + (ntb + nt) * 8 + 2 * tk;
        float b0 = bias[col], b1 = bias[col + 1];
        #pragma unroll
        for (int mt = 0; mt < 4; mt++) {
            int row0 = m0 + (mtb + mt) * 16 + g;
            float2 v0 = {c[mt][nt][0] + b0, c[mt][nt][1] + b1};
            float2 v1 = {c[mt][nt][2] + b0, c[mt][nt][3] + b1};
            __stcs((float2*)(C + (size_t)row0 * G4H + col), v0);
            __stcs((float2*)(C + (size_t)(row0 + 8) * G4H + col), v1);
        }
    }
}

// ---------------------------------------------------------------------------
// Stage h into A-fragment layout (fp16): af[(c*32+lane)*4 + r] uint32.
// ---------------------------------------------------------------------------
template <int NC>
__device__ __forceinline__ void stage_af(const float* __restrict__ src1,
                                         const float* __restrict__ src2,
                                         uint32_t* af) {
    const int tid = threadIdx.x;
    for (int i = tid; i < NC * 32; i += 512) {
        int c = i >> 5, lane = i & 31;
        int gr = lane >> 2, tc = lane & 3;
        int k0 = 16 * c + 2 * tc;
        const float* s = (NC == 32 || k0 < 512) ? (src1 + k0) : (src2 + k0 - 512);
        float2 f0 = *(const float2*)(s + gr * PROJ);
        float2 f1 = *(const float2*)(s + (gr + 8) * PROJ);
        float2 f2 = *(const float2*)(s + gr * PROJ + 8);
        float2 f3 = *(const float2*)(s + (gr + 8) * PROJ + 8);
        *(uint4*)(af + (size_t)i * 4) =
            make_uint4(h2u(f0), h2u(f1), h2u(f2), h2u(f3));
    }
}

// ---------------------------------------------------------------------------
// Gate phase via HMMA: xg prefetch hoisted; dual acc chains on the 64-k loop.
// ---------------------------------------------------------------------------
template <bool DO1, bool DO2>
__device__ __forceinline__ void gate_mma(
    const uint32_t* af, float* zbuf1, float* zbuf2,
    const float* __restrict__ xg1p, const float* __restrict__ xg2p)
{
    const int w = threadIdx.x >> 5, lane = threadIdx.x & 31;
    const int gate = w >> 2, jj8 = (w & 3) << 3;
    const int gr = lane >> 2, tc = lane & 3;
    const int ntg = gate * 512 + blockIdx.x * 4 + (w & 3);

    const int jl = jj8 + 2 * tc;
    const int rowg = gate * HID + blockIdx.x * 32 + jl;

    float2 x1a, x1b, x2a, x2b;
    if (DO1) {
        x1a = __ldcs((const float2*)(xg1p + (size_t)gr * G4H + rowg));
        x1b = __ldcs((const float2*)(xg1p + (size_t)(gr + 8) * G4H + rowg));
    }
    if (DO2) {
        x2a = __ldcs((const float2*)(xg2p + (size_t)gr * G4H + rowg));
        x2b = __ldcs((const float2*)(xg2p + (size_t)(gr + 8) * G4H + rowg));
    }

    float acc1[4] = {0.f, 0.f, 0.f, 0.f};
    float acc2[4] = {0.f, 0.f, 0.f, 0.f};
    float acc2b[4] = {0.f, 0.f, 0.f, 0.f};

    if (DO2) {
        const uint2* bp = g_pb2 + (size_t)ntg * 64 * 32 + lane;
        #pragma unroll 8
        for (int c = 0; c < 32; c++) {
            uint4 a0 = *(const uint4*)(af + (size_t)((2 * c) * 32 + lane) * 4);
            uint4 a1 = *(const uint4*)(af + (size_t)((2 * c + 1) * 32 + lane) * 4);
            uint2 b0 = bp[(size_t)(2 * c) * 32];
            uint2 b1 = bp[(size_t)(2 * c + 1) * 32];
            uint32_t af0[4] = {a0.x, a0.y, a0.z, a0.w};
            uint32_t af1[4] = {a1.x, a1.y, a1.z, a1.w};
            uint32_t bf0[2] = {b0.x, b0.y};
            uint32_t bf1[2] = {b1.x, b1.y};
            mma_f16(acc2, af0, bf0);
            mma_f16(acc2b, af1, bf1);
        }
    }
    if (DO1) {
        const uint2* bp = g_pb1 + (size_t)ntg * 32 * 32 + lane;
        #pragma unroll 8
        for (int c = 0; c < 32; c++) {
            uint4 av = *(const uint4*)(af + (size_t)(c * 32 + lane) * 4);
            uint2 bv = bp[(size_t)c * 32];
            uint32_t a[4] = {av.x, av.y, av.z, av.w};
            uint32_t b[2] = {bv.x, bv.y};
            mma_f16(acc1, a, b);
        }
    }

    if (DO1) {
        float2 z0 = {acc1[0] + x1a.x, acc1[1] + x1a.y};
        float2 z1 = {acc1[2] + x1b.x, acc1[3] + x1b.y};
        *(float2*)&zbuf1[gate * 512 + gr * 32 + jl] = z0;
        *(float2*)&zbuf1[gate * 512 + (gr + 8) * 32 + jl] = z1;
    }
    if (DO2) {
        float2 z0 = {acc2[0] + acc2b[0] + x2a.x, acc2[1] + acc2b[1] + x2a.y};
        float2 z1 = {acc2[2] + acc2b[2] + x2b.x, acc2[3] + acc2b[3] + x2b.y};
        *(float2*)&zbuf2[gate * 512 + gr * 32 + jl] = z0;
        *(float2*)&zbuf2[gate * 512 + (gr + 8) * 32 + jl] = z1;
    }
}

// ---------------------------------------------------------------------------
// Cell update: writes gh to SHARED memory (read by cluster peers via DSMEM).
// ---------------------------------------------------------------------------
template <bool DO1, bool DO2>
__device__ __forceinline__ void cell_update(
    const float* zbuf1, const float* zbuf2, float* gh_s,
    float& c1r, float& c2r, bool last1, bool last2)
{
    const int tid = threadIdx.x;
    const int b = tid >> 5, jl = tid & 31;
    const size_t off = (size_t)b * HID + blockIdx.x * 32 + jl;
    if (DO1) {
        float zi = zbuf1[0 * 512 + b * 32 + jl];
        float zf = zbuf1[1 * 512 + b * 32 + jl];
        float zg = zbuf1[2 * 512 + b * 32 + jl];
        float zo = zbuf1[3 * 512 + b * 32 + jl];
        float cn = sigf(zf) * c1r + sigf(zi) * tanhf(zg);
        c1r = cn;
        gh_s[b * 32 + jl] = sigf(zo) * tanhf(cn);
        if (last1) g_c1[off] = cn;
    }
    if (DO2) {
        float zi = zbuf2[0 * 512 + b * 32 + jl];
        float zf = zbuf2[1 * 512 + b * 32 + jl];
        float zg = zbuf2[2 * 512 + b * 32 + jl];
        float zo = zbuf2[3 * 512 + b * 32 + jl];
        float cn = sigf(zf) * c2r + sigf(zi) * tanhf(zg);
        c2r = cn;
        gh_s[512 + b * 32 + jl] = sigf(zo) * tanhf(cn);
        if (last2) g_c2[off] = cn;
    }
}

// ---------------------------------------------------------------------------
// Proj staging via DSMEM: read gh fragments from the 4 cluster ranks.
// ---------------------------------------------------------------------------
template <bool DO1, bool DO2>
__device__ __forceinline__ void stage_paf(const float* gh_s,
                                          uint32_t* paf1, uint32_t* paf2) {
    const int tid = threadIdx.x;
    const int layer = tid >> 8;
    if ((layer == 0 && !DO1) || (layer == 1 && !DO2)) return;
    const int i = tid & 255;
    const int cl = i >> 5, lane = i & 31;
    const int gr = lane >> 2, tc = lane & 3;
    const int rank = cl >> 1;
    const int jloc = 16 * (cl & 1) + 2 * tc;
    uint32_t base = s2u(gh_s) + (uint32_t)(layer * 512 * 4);
    uint32_t rbase = mapa_rank(base, rank);
    float2 f0 = ld_ds2(rbase + (uint32_t)((gr * 32 + jloc) * 4));
    float2 f1 = ld_ds2(rbase + (uint32_t)(((gr + 8) * 32 + jloc) * 4));
    float2 f2 = ld_ds2(rbase + (uint32_t)((gr * 32 + jloc + 8) * 4));
    float2 f3 = ld_ds2(rbase + (uint32_t)(((gr + 8) * 32 + jloc + 8) * 4));
    uint32_t* paf = layer ? paf2 : paf1;
    *(uint4*)(paf + (size_t)i * 4) = make_uint4(h2u(f0), h2u(f1), h2u(f2), h2u(f3));
}

template <bool DO1, bool DO2>
__device__ __forceinline__ void proj_mma(
    const uint32_t* paf1, const uint32_t* paf2,
    float* __restrict__ hout1, float* __restrict__ hout2, int pt, int kc)
{
    const int w = threadIdx.x >> 5, lane = threadIdx.x & 31;
    const int gr = lane >> 2, tc = lane & 3;
    const int ntg = pt * 16 + w;
    const int pg = ntg * 8 + 2 * tc;

    if (DO1) {
        float acc[4] = {0.f, 0.f, 0.f, 0.f};
        const uint2* bp = g_pr1 + ((size_t)ntg * 256 + kc * 8) * 32 + lane;
        #pragma unroll
        for (int cl = 0; cl < 8; cl++) {
            uint4 av = *(const uint4*)(paf1 + (size_t)(cl * 32 + lane) * 4);
            uint2 bv = bp[(size_t)cl * 32];
            uint32_t a[4] = {av.x, av.y, av.z, av.w};
            uint32_t b[2] = {bv.x, bv.y};
            mma_f16(acc, a, b);
        }
        atomicAdd(hout1 + (size_t)gr * PROJ + pg,           acc[0]);
        atomicAdd(hout1 + (size_t)gr * PROJ + pg + 1,       acc[1]);
        atomicAdd(hout1 + (size_t)(gr + 8) * PROJ + pg,     acc[2]);
        atomicAdd(hout1 + (size_t)(gr + 8) * PROJ + pg + 1, acc[3]);
    }
    if (DO2) {
        float acc[4] = {0.f, 0.f, 0.f, 0.f};
        const uint2* bp = g_pr2 + ((size_t)ntg * 256 + kc * 8) * 32 + lane;
        #pragma unroll
        for (int cl = 0; cl < 8; cl++) {
            uint4 av = *(const uint4*)(paf2 + (size_t)(cl * 32 + lane) * 4);
            uint2 bv = bp[(size_t)cl * 32];
            uint32_t a[4] = {av.x, av.y, av.z, av.w};
            uint32_t b[2] = {bv.x, bv.y};
            mma_f16(acc, a, b);
        }
        atomicAdd(hout2 + (size_t)gr * PROJ + pg,           acc[0]);
        atomicAdd(hout2 + (size_t)gr * PROJ + pg + 1,       acc[1]);
        atomicAdd(hout2 + (size_t)(gr + 8) * PROJ + pg,     acc[2]);
        atomicAdd(hout2 + (size_t)(gr + 8) * PROJ + pg + 1, acc[3]);
    }
}

// ---------------------------------------------------------------------------
// Persistent recurrence: clusters of 4; gh passes through DSMEM; one grid
// barrier per step.
// ---------------------------------------------------------------------------
__global__ void __launch_bounds__(512, 1) __cluster_dims__(CLSZ, 1, 1)
recurrence_kernel() {
    extern __shared__ float smem[];
    uint32_t* af = (uint32_t*)smem;                  // [0, 8192) uint32
    float* zbuf1 = smem + 8192;
    float* zbuf2 = smem + 10240;
    float* gh_s  = smem + SM_GH_OFF;                 // [2][16][32]
    uint32_t* paf1 = (uint32_t*)smem;                // proj aliases
    uint32_t* paf2 = (uint32_t*)smem + 1024;

    const int pt = blockIdx.x & 3;
    const int kc = blockIdx.x >> 2;

    unsigned gen = g_genv;
    float c1r = 0.f, c2r = 0.f;

    // ---- prologue: G1(0) ----
    stage_af<32>(g_out1, nullptr, af);
    __syncthreads();
    gate_mma<true, false>(af, zbuf1, zbuf2, g_xg1, nullptr);
    __syncthreads();
    cell_update<true, false>(zbuf1, zbuf2, gh_s, c1r, c2r, false, false);
    cluster_sync_();
    stage_paf<true, false>(gh_s, paf1, paf2);
    __syncthreads();
    proj_mma<true, false>(paf1, paf2,
                          g_out1 + (size_t)1 * (BATCH * PROJ), nullptr, pt, kc);
    gsync(gen);

    for (int t = 0; t < T_STEPS - 1; t++) {
        // gate phase: G1(t+1) + G2(t)
        stage_af<64>(g_out1 + (size_t)(t + 1) * (BATCH * PROJ),
                     g_out2 + (size_t)t * (BATCH * PROJ), af);
        __syncthreads();
        gate_mma<true, true>(af, zbuf1, zbuf2,
                             g_xg1 + (size_t)(t + 1) * BATCH * G4H,
                             g_xg2 + (size_t)t * BATCH * G4H);
        __syncthreads();
        cell_update<true, true>(zbuf1, zbuf2, gh_s, c1r, c2r,
                                (t + 1 == T_STEPS - 1), false);
        cluster_sync_();                      // gh_s visible within cluster
        // proj phase: P1(t+1) + P2(t) via DSMEM
        stage_paf<true, true>(gh_s, paf1, paf2);
        __syncthreads();
        proj_mma<true, true>(paf1, paf2,
                             g_out1 + (size_t)(t + 2) * (BATCH * PROJ),
                             g_out2 + (size_t)(t + 1) * (BATCH * PROJ), pt, kc);
        gsync(gen);                           // single grid barrier per step
    }

    // ---- tail: G2(255) | P2(255) ----
    {
        int t = T_STEPS - 1;
        stage_af<64>(g_out1 + (size_t)(t + 1) * (BATCH * PROJ),
                     g_out2 + (size_t)t * (BATCH * PROJ), af);
        __syncthreads();
        gate_mma<false, true>(af, zbuf1, zbuf2, nullptr,
                              g_xg2 + (size_t)t * BATCH * G4H);
        __syncthreads();
        cell_update<false, true>(zbuf1, zbuf2, gh_s, c1r, c2r, false, true);
        cluster_sync_();
        stage_paf<false, true>(gh_s, paf1, paf2);
        __syncthreads();
        proj_mma<false, true>(paf1, paf2, nullptr,
                              g_out2 + (size_t)(t + 1) * (BATCH * PROJ), pt, kc);
        cluster_sync_();                      // peers done reading gh_s before exit
    }
}

// ---------------------------------------------------------------------------
// Heads: one warp per packed token
// ---------------------------------------------------------------------------
__global__ void __launch_bounds__(512) heads_kernel(
    const float* __restrict__ Wp, const float* __restrict__ bp,
    const float* __restrict__ Wa, const float* __restrict__ ba,
    float* __restrict__ out, int total) {
    const int t = blockIdx.x;
    const int w = threadIdx.x >> 5;
    const int lane = threadIdx.x & 31;
    if (w >= g_counts[t]) return;
    const int b = w;
    const int tok = g_offsets[t] + b;

    const float* o1 = g_out1 + (size_t)(t + 1) * (BATCH * PROJ) + (size_t)b * PROJ;
    const float* o2 = g_out2 + (size_t)(t + 1) * (BATCH * PROJ) + (size_t)b * PROJ;
    float v[16];
    #pragma unroll
    for (int i = 0; i < 16; i++) v[i] = o1[lane + 32 * i] + o2[lane + 32 * i];

    __shared__ float sp[16][20];
    __shared__ float sa[16][20];
    #pragma unroll
    for (int o = 0; o < 20; o++) {
        float s1 = 0.f, s2 = 0.f;
        #pragma unroll
        for (int i = 0; i < 16; i++) {
            float x = v[i];
            s1 = fmaf(x, Wp[o * PROJ + lane + 32 * i], s1);
            s2 = fmaf(x, Wa[o * PROJ + lane + 32 * i], s2);
        }
        #pragma unroll
        for (int off = 16; off; off >>= 1) {
            s1 += __shfl_xor_sync(0xffffffffu, s1, off);
            s2 += __shfl_xor_sync(0xffffffffu, s2, off);
        }
        if (lane == 0) { sp[w][o] = s1 + bp[o]; sa[w][o] = s2 + ba[o]; }
    }
    __syncwarp();
    if (lane == 0) {
        float m = -1e30f;
        #pragma unroll
        for (int o = 0; o < 20; o++) m = fmaxf(m, sp[w][o]);
        float e[20], sum = 0.f;
        #pragma unroll
        for (int o = 0; o < 20; o++) { e[o] = expf(sp[w][o] - m); sum += e[o]; }
        float inv = 1.f / sum;
        float* aa = out + (size_t)total * 20;
        #pragma unroll
        for (int o = 0; o < 20; o++) {
            out[(size_t)tok * 20 + o] = e[o] * inv;
            aa[(size_t)tok * 20 + o]  = sa[w][o];
        }
    }
}

// ---------------------------------------------------------------------------
// Final states: h1, c1, h2, c2
// ---------------------------------------------------------------------------
__global__ void finalize_kernel(float* __restrict__ out, int total) {
    const size_t base = (size_t)total * 40;
    const int nH = BATCH * PROJ;
    const int nC = BATCH * HID;
    int idx = blockIdx.x * blockDim.x + threadIdx.x;
    if (idx >= 2 * (nH + nC)) return;
    float v;
    if (idx < nH)                v = g_out1[(size_t)T_STEPS * nH + idx];
    else if (idx < nH + nC)      v = g_c1[idx - nH];
    else if (idx < 2 * nH + nC)  v = g_out2[(size_t)T_STEPS * nH + (idx - nH - nC)];
    else                         v = g_c2[idx - 2 * nH - nC];
    out[base + idx] = v;
}

// ---------------------------------------------------------------------------
// Host launch
// ---------------------------------------------------------------------------
extern "C" void kernel_launch(void* const* d_in, const int* in_sizes, int n_in,
                              void* d_out, int out_size) {
    const float* uncon  = (const float*)d_in[0];
    const float* con    = (const float*)d_in[1];
    const int*   lens   = (const int*)d_in[2];
    const float* W_ih1  = (const float*)d_in[3];
    const float* b1     = (const float*)d_in[4];
    const float* W_hh1  = (const float*)d_in[5];
    const float* W_hr1  = (const float*)d_in[6];
    const float* W_ih2  = (const float*)d_in[7];
    const float* b2     = (const float*)d_in[8];
    const float* W_hh2  = (const float*)d_in[9];
    const float* W_hr2  = (const float*)d_in[10];
    const float* W_pssm = (const float*)d_in[11];
    const float* b_pssm = (const float*)d_in[12];
    const float* W_aa   = (const float*)d_in[13];
    const float* b_aa   = (const float*)d_in[14];
    float* out = (float*)d_out;

    const int total = (out_size - 2 * (BATCH * PROJ + BATCH * HID)) / 40;

    float *p_xg1, *p_xg2;
    cudaGetSymbolAddress((void**)&p_xg1, g_xg1);
    cudaGetSymbolAddress((void**)&p_xg2, g_xg2);

    cudaFuncSetAttribute(recurrence_kernel,
                         cudaFuncAttributeMaxDynamicSharedMemorySize, SM_TOTAL_B);

    // 1: fused prep (HMMA fragment packs + zero + counts)
    prep_kernel<<<10241, 256>>>(W_hh1, W_ih2, W_hh2, W_hr1, W_hr2, lens);
    // 2,3: Phase A on tensor cores (3xFP16 split HMMA)
    sgemm_f16<<<dim3(G4H / 128, (T_STEPS * BATCH) / 128), 256>>>(
        uncon, W_ih1, b1, p_xg1, F1, F1, F1, 0);
    sgemm_f16<<<dim3(G4H / 128, (T_STEPS * BATCH) / 128), 256>>>(
        con, W_ih2, b2, p_xg2, F2CON, F2CON, 1280, 512);
    // 4: persistent recurrence (clusters of 4, gh via DSMEM, 1 barrier/step)
    recurrence_kernel<<<NBLK, 512, SM_TOTAL_B>>>();
    // 5,6: heads + final states
    heads_kernel<<<T_STEPS, 512>>>(W_pssm, b_pssm, W_aa, b_aa, out, total);
    finalize_kernel<<<(2 * (BATCH * PROJ + BATCH * HID) + 255) / 256, 256>>>(out, total);
}